// round 5
// baseline (speedup 1.0000x reference)
#include <cuda_runtime.h>

#define TPB  512
#define ST   17            // padded row stride (float2 units)
#define SITE (32*ST)       // 544 float2 per site tensor

__device__ __forceinline__ void cmac(float2& acc, float2 a, float2 b) {        // acc += a*b
    acc.x = fmaf(a.x, b.x, fmaf(-a.y, b.y, acc.x));
    acc.y = fmaf(a.x, b.y, fmaf( a.y, b.x, acc.y));
}
__device__ __forceinline__ void cmacc(float2& acc, float2 a, float2 b) {       // acc += a*conj(b)
    acc.x = fmaf(a.x, b.x, fmaf( a.y, b.y, acc.x));
    acc.y = fmaf(a.y, b.x, fmaf(-a.x, b.y, acc.y));
}

// smem: bufA 18*544 | bufB 18*544 | Ush 72 | Msct 544 | Msc 512 | Renv 256 | Lenv 768 | red 32f
#define F2_TOTAL (2*18*SITE + 72 + SITE + 512 + 256 + 768)
#define SMEM_BYTES (F2_TOTAL*8 + 32*4)

// Renv <- sum_s A_j^s . Renv . A_j^s(dagger), chi=16. 512-thread wide, broadcast-friendly.
__device__ __forceinline__ void transfer(const float2* __restrict__ Aj,
                                         float2* __restrict__ Renv,
                                         float2* __restrict__ Msct, int t)
{
    // phase 1: M = A (32x16) . Renv (16x16); 1 output/thread; write conj-transposed
    {
        const int r = t >> 4, bp = t & 15;          // warp: 2 distinct r -> A broadcast
        const float2* row = Aj + r*ST;
        float2 acc = make_float2(0.f,0.f);
#pragma unroll
        for (int be = 0; be < 16; ++be)
            cmac(acc, row[be], Renv[be*16 + bp]);
        const int s = r & 1, al = r >> 1;
        Msct[(s*16 + bp)*ST + al] = make_float2(acc.x, -acc.y);
    }
    __syncthreads();
    // phase 2: P[a2][a1] = sum_k A[a2][k]*Msct[k][a1]; Renv[a1][a2] = conj(P)
    if (t < 256) {
        const int a1 = t & 15, a2 = t >> 4;         // warp: a1 spans 16 banks, a2 2 rows
        const float2* arow0 = Aj + (a2*2)*ST;
        const float2* arow1 = arow0 + ST;
        float2 P0 = make_float2(0.f,0.f), P1 = make_float2(0.f,0.f);
#pragma unroll
        for (int c = 0; c < 16; ++c) {
            cmac(P0, arow0[c], Msct[c*ST + a1]);
            cmac(P1, arow1[c], Msct[(16+c)*ST + a1]);
        }
        Renv[a1*16 + a2] = make_float2(P0.x + P1.x, -(P0.y + P1.y));
    }
    __syncthreads();
}

__global__ void __launch_bounds__(TPB, 1) vqc_mps_kernel(
    const float* __restrict__ w, const int* __restrict__ x, float* __restrict__ out)
{
    extern __shared__ float2 sm[];
    float2* bufA = sm;
    float2* bufB = bufA + 18*SITE;
    float2* Ush  = bufB + 18*SITE;
    float2* Msct = Ush + 72;
    float2* Msc  = Msct + SITE;
    float2* Renv = Msc + 512;
    float2* Lenv = Renv + 256;
    float*  red  = (float*)(Lenv + 768);

    const int b = blockIdx.x, t = threadIdx.x;
    const int lane = t & 31, wid = t >> 5;

    // product state |x_0..x_8, 0..0>
    if (t < 18) {
        int bit = (t < 9) ? x[b*9 + t] : 0;
        bufA[t*SITE + 0 ] = make_float2(bit == 0 ? 1.f : 0.f, 0.f);
        bufA[t*SITE + ST] = make_float2(bit == 1 ? 1.f : 0.f, 0.f);
    }
    __syncthreads();

    float2* A  = bufA;
    float2* Bb = bufB;

    // ---- 4 layers: fused (rotation + CNOT-staircase MPO), chi: c -> 2c ----
    for (int l = 0; l < 4; ++l) {
        const int c2 = 2 << l;
        const int cm = (1 << l) - 1;

        if (t < 18) {
            float phi = w[(l*18 + t)*3 + 0];
            float th  = w[(l*18 + t)*3 + 1];
            float om  = w[(l*18 + t)*3 + 2];
            float sh, ch; sincosf(0.5f*th, &sh, &ch);
            float sa, ca; sincosf(-0.5f*(phi + om), &sa, &ca);
            float sb, cb; sincosf( 0.5f*(phi - om), &sb, &cb);
            Ush[t*4+0] = make_float2( ca*ch,  sa*ch);
            Ush[t*4+1] = make_float2(-cb*sh, -sb*sh);
            Ush[t*4+2] = make_float2( cb*sh, -sb*sh);
            Ush[t*4+3] = make_float2( ca*ch, -sa*ch);
        }
        __syncthreads();

        for (int j = 0; j < 18; ++j) {
            const int Lo = (j == 0)  ? 1 : c2;
            const int Ro = (j == 17) ? 1 : c2;
            const int n  = Lo * 2 * Ro;
            const float2* Aj = A  + j*SITE;
            float2*       Bj = Bb + j*SITE;
            const float2 U00 = Ush[j*4+0], U01 = Ush[j*4+1];
            const float2 U10 = Ush[j*4+2], U11 = Ush[j*4+3];
            for (int i = t; i < n; i += TPB) {
                int bp, rest;
                if (j == 17) { bp = 0;           rest = i; }
                else         { bp = i & (c2-1);  rest = i >> (l+1); }
                const int s  = rest & 1;
                const int ap = rest >> 1;
                const int a  = (j == 0)  ? 0 : (ap >> l);
                const int al = (j == 0)  ? 0 : (ap & cm);
                const int kb = (j == 17) ? s : (bp >> l);
                const int be = (j == 17) ? 0 : (bp & cm);
                float2 v = make_float2(0.f, 0.f);
                if (kb == s) {
                    const int u = s ^ a;
                    float2 A0 = Aj[al*(2*ST) + be];
                    float2 A1 = Aj[al*(2*ST) + ST + be];
                    float2 Ua = (u == 0) ? U00 : U10;
                    float2 Ub = (u == 0) ? U01 : U11;
                    cmac(v, Ua, A0);
                    cmac(v, Ub, A1);
                }
                Bj[(ap*2 + s)*ST + bp] = v;
            }
        }
        __syncthreads();
        float2* tmp = A; A = Bb; Bb = tmp;
    }

    // ---- contraction, chi=16 everywhere ----

    // Renv init from site 17 (right dim 1)
    if (t < 256) {
        const int a1 = t >> 4, a2 = t & 15;
        const float2* A17 = A + 17*SITE;
        float2 acc = make_float2(0.f,0.f);
        cmacc(acc, A17[(a1*2  )*ST], A17[(a2*2  )*ST]);
        cmacc(acc, A17[(a1*2+1)*ST], A17[(a2*2+1)*ST]);
        Renv[a1*16 + a2] = acc;
    }
    __syncthreads();

    for (int j = 16; j >= 4; --j) transfer(A + j*SITE, Renv, Msct, t);

    // left environments L0,L1,L2
    if (t < 256) {
        const int b1 = t >> 4, b2 = t & 15;
        const float2* A0 = A;
        float2 acc = make_float2(0.f,0.f);
        cmacc(acc, A0[b1],      A0[b2]);
        cmacc(acc, A0[ST + b1], A0[ST + b2]);
        Lenv[t] = acc;
    }
    __syncthreads();
    for (int m = 1; m <= 2; ++m) {
        const float2* Lp = Lenv + (m-1)*256;
        float2*       Ln = Lenv + m*256;
        const float2* Am = A + m*SITE;
        // Msc[b2][s][g] = sum_b1 Lp[b1][b2] * Am[(b1,s)][g]  (512 outs, 1/thread)
        {
            const int g = t & 15, s = (t >> 4) & 1, b2 = t >> 5;
            float2 acc = make_float2(0.f,0.f);
#pragma unroll
            for (int b1 = 0; b1 < 16; ++b1)
                cmac(acc, Lp[b1*16 + b2], Am[(b1*2 + s)*ST + g]);
            Msc[b2*32 + s*16 + g] = acc;
        }
        __syncthreads();
        // Ln[g1][g2] = sum_{b2,s} Msc[b2][s][g1] * conj(Am[(b2,s)][g2])
        if (t < 256) {
            const int g1 = t >> 4, g2 = t & 15;
            float2 acc = make_float2(0.f,0.f);
#pragma unroll
            for (int kk = 0; kk < 32; ++kk)
                cmacc(acc, Msc[(kk>>1)*32 + (kk&1)*16 + g1], Am[kk*ST + g2]);
            Ln[t] = acc;
        }
        __syncthreads();
    }

    // ---- EVs q=3..0 ----
    for (int q = 3; q >= 0; --q) {
        const float2* Aq = A + q*SITE;

        // phase A: X[(al,s)][bp] = sum_be Aq[(al,s)][be] * Renv[be][bp]  (1/thread)
        {
            const int r = t >> 4, bp = t & 15;
            const float2* row = Aq + r*ST;
            float2 acc = make_float2(0.f,0.f);
#pragma unroll
            for (int be = 0; be < 16; ++be)
                cmac(acc, row[be], Renv[be*16 + bp]);
            Msc[r*16 + bp] = acc;
        }
        __syncthreads();

        // phase B: signed contributions + reduction over 16 warps.
        // ALL 512 threads participate for q>0: a2 = t>>5 spans 0..15 (R4 bug fix).
        float num = 0.f, den = 0.f;
        if (q == 0) {
            if (t < 32) {
                const int s = t >> 4, bp = t & 15;
                float2 z  = Msc[s*16 + bp];
                float2 av = Aq[s*ST + bp];
                float v = z.x*av.x + z.y*av.y;
                num = s ? -v : v;  den = v;
            }
        } else {
            const float2* Lp = Lenv + (q-1)*256;
            const int bp = t & 15, s = (t >> 4) & 1, a2 = t >> 5;
            float2 z = make_float2(0.f,0.f);
#pragma unroll
            for (int al = 0; al < 16; ++al)
                cmac(z, Lp[al*16 + a2], Msc[(al*2 + s)*16 + bp]);
            float2 av = Aq[(a2*2 + s)*ST + bp];
            float v = z.x*av.x + z.y*av.y;
            num = s ? -v : v;  den = v;
        }
#pragma unroll
        for (int o = 16; o > 0; o >>= 1) {
            num += __shfl_xor_sync(0xffffffffu, num, o);
            den += __shfl_xor_sync(0xffffffffu, den, o);
        }
        if (lane == 0) { red[wid*2] = num; red[wid*2+1] = den; }
        __syncthreads();
        if (t == 0) {
            float N = 0.f, D = 0.f;
#pragma unroll
            for (int wdx = 0; wdx < 16; ++wdx) { N += red[wdx*2]; D += red[wdx*2+1]; }
            out[b*4 + q] = N / D;
        }
        if (q > 0) transfer(Aq, Renv, Msct, t);
    }
}

extern "C" void kernel_launch(void* const* d_in, const int* in_sizes, int n_in,
                              void* d_out, int out_size) {
    const float* w;
    const int*   xin;
    if (n_in >= 2 && in_sizes[0] == 4*18*3) {
        w   = (const float*)d_in[0];
        xin = (const int*)  d_in[1];
    } else {
        w   = (const float*)d_in[1];
        xin = (const int*)  d_in[0];
    }
    float* out = (float*)d_out;

    cudaFuncSetAttribute(vqc_mps_kernel,
                         cudaFuncAttributeMaxDynamicSharedMemorySize,
                         (int)SMEM_BYTES);
    vqc_mps_kernel<<<64, TPB, SMEM_BYTES>>>(w, xin, out);
}

// round 6
// speedup vs baseline: 1.0592x; 1.0592x over previous
#include <cuda_runtime.h>

#define TPB  256
#define ST   17            // padded row stride (float2 units)
#define SITE (32*ST)       // 544 float2 per site tensor

__device__ __forceinline__ void cmac(float2& acc, float2 a, float2 b) {        // acc += a*b
    acc.x = fmaf(a.x, b.x, fmaf(-a.y, b.y, acc.x));
    acc.y = fmaf(a.x, b.y, fmaf( a.y, b.x, acc.y));
}
__device__ __forceinline__ void cmacc(float2& acc, float2 a, float2 b) {       // acc += a*conj(b)
    acc.x = fmaf(a.x, b.x, fmaf( a.y, b.y, acc.x));
    acc.y = fmaf(a.y, b.x, fmaf(-a.x, b.y, acc.y));
}

// smem: bufA 18*544 | bufB 18*544 | Ush 72 | Msct 544 | Msc 512 | Renv 256 | Lenv 768 | red 16f
#define F2_TOTAL (2*18*SITE + 72 + SITE + 512 + 256 + 768)
#define SMEM_BYTES (F2_TOTAL*8 + 16*4)

// transfer phase 1: M[(al,s)][bp] = sum_be Aj[(al,s)][be] * Renv[be][bp]
// thread (r = t>>3, bp0 = (t&7)*2) computes 2 adjacent-bp outputs.
// Renv loads are float4 (two adjacent complex), conflict-free; 4 indep acc chains.
// Writes conj-transposed Msct always; optionally Msc (for EV phase B).
__device__ __forceinline__ void transfer_p1(const float2* __restrict__ Aj,
                                            const float2* __restrict__ Renv,
                                            float2* __restrict__ Msct,
                                            float2* __restrict__ Msc, int t)
{
    const int r = t >> 3, bpq = t & 7, bp0 = bpq * 2;
    const float4* R4 = (const float4*)Renv;      // Renv is 16B-aligned
    float4 rv[16];
#pragma unroll
    for (int be = 0; be < 16; ++be) rv[be] = R4[be*8 + bpq];

    const float2* row = Aj + r*ST;
    float2 e0 = make_float2(0.f,0.f), o0 = make_float2(0.f,0.f);
    float2 e1 = make_float2(0.f,0.f), o1 = make_float2(0.f,0.f);
#pragma unroll
    for (int be = 0; be < 16; be += 2) {
        float2 a0 = row[be], a1 = row[be+1];
        cmac(e0, a0, make_float2(rv[be].x,   rv[be].y));
        cmac(e1, a0, make_float2(rv[be].z,   rv[be].w));
        cmac(o0, a1, make_float2(rv[be+1].x, rv[be+1].y));
        cmac(o1, a1, make_float2(rv[be+1].z, rv[be+1].w));
    }
    const float2 out0 = make_float2(e0.x + o0.x, e0.y + o0.y);
    const float2 out1 = make_float2(e1.x + o1.x, e1.y + o1.y);
    const int s = r & 1, al = r >> 1;
    Msct[(s*16 + bp0  )*ST + al] = make_float2(out0.x, -out0.y);
    Msct[(s*16 + bp0+1)*ST + al] = make_float2(out1.x, -out1.y);
    if (Msc) {
        Msc[r*16 + bp0  ] = out0;
        Msc[r*16 + bp0+1] = out1;
    }
}

// transfer phase 2: Renv[a1][a2] = conj( sum_k Aj[a2][k] * Msct[k][a1] )
__device__ __forceinline__ void transfer_p2(const float2* __restrict__ Aj,
                                            float2* __restrict__ Renv,
                                            const float2* __restrict__ Msct, int t)
{
    const int a1 = t & 15, a2 = t >> 4;
    const float2* ar0 = Aj + (a2*2)*ST;
    const float2* ar1 = ar0 + ST;
    float2 p0 = make_float2(0.f,0.f), p1 = make_float2(0.f,0.f);
    float2 p2 = make_float2(0.f,0.f), p3 = make_float2(0.f,0.f);
#pragma unroll
    for (int c = 0; c < 16; c += 2) {
        cmac(p0, ar0[c  ], Msct[(c   )*ST + a1]);
        cmac(p1, ar0[c+1], Msct[(c+1 )*ST + a1]);
        cmac(p2, ar1[c  ], Msct[(16+c)*ST + a1]);
        cmac(p3, ar1[c+1], Msct[(17+c)*ST + a1]);
    }
    Renv[a1*16 + a2] = make_float2(p0.x+p1.x+p2.x+p3.x, -(p0.y+p1.y+p2.y+p3.y));
}

__global__ void __launch_bounds__(TPB, 1) vqc_mps_kernel(
    const float* __restrict__ w, const int* __restrict__ x, float* __restrict__ out)
{
    extern __shared__ float2 sm[];
    float2* bufA = sm;
    float2* bufB = bufA + 18*SITE;
    float2* Ush  = bufB + 18*SITE;
    float2* Msct = Ush + 72;
    float2* Msc  = Msct + SITE;
    float2* Renv = Msc + 512;
    float2* Lenv = Renv + 256;
    float*  red  = (float*)(Lenv + 768);

    const int b = blockIdx.x, t = threadIdx.x;
    const int lane = t & 31, wid = t >> 5;

    // product state |x_0..x_8, 0..0>
    if (t < 18) {
        int bit = (t < 9) ? x[b*9 + t] : 0;
        bufA[t*SITE + 0 ] = make_float2(bit == 0 ? 1.f : 0.f, 0.f);
        bufA[t*SITE + ST] = make_float2(bit == 1 ? 1.f : 0.f, 0.f);
    }
    __syncthreads();

    float2* A  = bufA;
    float2* Bb = bufB;

    // ---- 4 layers: fused (rotation + CNOT-staircase MPO), chi: c -> 2c ----
    for (int l = 0; l < 4; ++l) {
        const int c2 = 2 << l;
        const int cm = (1 << l) - 1;

        if (t < 18) {
            float phi = w[(l*18 + t)*3 + 0];
            float th  = w[(l*18 + t)*3 + 1];
            float om  = w[(l*18 + t)*3 + 2];
            float sh, ch; sincosf(0.5f*th, &sh, &ch);
            float sa, ca; sincosf(-0.5f*(phi + om), &sa, &ca);
            float sb, cb; sincosf( 0.5f*(phi - om), &sb, &cb);
            Ush[t*4+0] = make_float2( ca*ch,  sa*ch);
            Ush[t*4+1] = make_float2(-cb*sh, -sb*sh);
            Ush[t*4+2] = make_float2( cb*sh, -sb*sh);
            Ush[t*4+3] = make_float2( ca*ch, -sa*ch);
        }
        __syncthreads();

        for (int j = 0; j < 18; ++j) {
            const int Lo = (j == 0)  ? 1 : c2;
            const int Ro = (j == 17) ? 1 : c2;
            const int n  = Lo * 2 * Ro;
            const float2* Aj = A  + j*SITE;
            float2*       Bj = Bb + j*SITE;
            const float2 U00 = Ush[j*4+0], U01 = Ush[j*4+1];
            const float2 U10 = Ush[j*4+2], U11 = Ush[j*4+3];
            for (int i = t; i < n; i += TPB) {
                int bp, rest;
                if (j == 17) { bp = 0;           rest = i; }
                else         { bp = i & (c2-1);  rest = i >> (l+1); }
                const int s  = rest & 1;
                const int ap = rest >> 1;
                const int a  = (j == 0)  ? 0 : (ap >> l);
                const int al = (j == 0)  ? 0 : (ap & cm);
                const int kb = (j == 17) ? s : (bp >> l);
                const int be = (j == 17) ? 0 : (bp & cm);
                float2 v = make_float2(0.f, 0.f);
                if (kb == s) {
                    const int u = s ^ a;
                    float2 A0 = Aj[al*(2*ST) + be];
                    float2 A1 = Aj[al*(2*ST) + ST + be];
                    float2 Ua = (u == 0) ? U00 : U10;
                    float2 Ub = (u == 0) ? U01 : U11;
                    cmac(v, Ua, A0);
                    cmac(v, Ub, A1);
                }
                Bj[(ap*2 + s)*ST + bp] = v;
            }
        }
        __syncthreads();
        float2* tmp = A; A = Bb; Bb = tmp;
    }

    // ---- fused phase: Renv init (site 17 Gram) + L0 init ----
    {
        const int i1 = t >> 4, i2 = t & 15;
        const float2* A17 = A + 17*SITE;
        float2 acc = make_float2(0.f,0.f);
        cmacc(acc, A17[(i1*2  )*ST], A17[(i2*2  )*ST]);
        cmacc(acc, A17[(i1*2+1)*ST], A17[(i2*2+1)*ST]);
        Renv[i1*16 + i2] = acc;

        const float2* A0 = A;
        float2 lcc = make_float2(0.f,0.f);
        cmacc(lcc, A0[i1],      A0[i2]);
        cmacc(lcc, A0[ST + i1], A0[ST + i2]);
        Lenv[t] = lcc;
    }
    __syncthreads();

    // ---- R-chain j = 16..4 ----
    for (int j = 16; j >= 4; --j) {
        transfer_p1(A + j*SITE, Renv, Msct, nullptr, t);
        __syncthreads();
        transfer_p2(A + j*SITE, Renv, Msct, t);
        __syncthreads();
    }

    // ---- left environments L1, L2 ----
    for (int m = 1; m <= 2; ++m) {
        const float2* Lp = Lenv + (m-1)*256;
        float2*       Ln = Lenv + m*256;
        const float2* Am = A + m*SITE;
        {
            const int g = t & 15, s = (t >> 4) & 1, b2a = t >> 5;
            float2 acc0 = make_float2(0.f,0.f), acc1 = make_float2(0.f,0.f);
#pragma unroll
            for (int b1 = 0; b1 < 16; ++b1) {
                float2 av = Am[(b1*2 + s)*ST + g];
                cmac(acc0, Lp[b1*16 + b2a    ], av);
                cmac(acc1, Lp[b1*16 + b2a + 8], av);
            }
            Msc[ b2a     *32 + s*16 + g] = acc0;
            Msc[(b2a + 8)*32 + s*16 + g] = acc1;
        }
        __syncthreads();
        {
            const int g1 = t >> 4, g2 = t & 15;
            float2 acc = make_float2(0.f,0.f);
#pragma unroll
            for (int kk = 0; kk < 32; ++kk)
                cmacc(acc, Msc[(kk>>1)*32 + (kk&1)*16 + g1], Am[kk*ST + g2]);
            Ln[t] = acc;
        }
        __syncthreads();
    }

    // ---- EVs q=3..0 (phase A of q == transfer p1 of q, fused) ----
    transfer_p1(A + 3*SITE, Renv, Msct, Msc, t);      // phase A for q=3
    __syncthreads();

    for (int q = 3; q >= 1; --q) {
        const float2* Aq = A + q*SITE;

        // fused phase: transfer p2 (Renv -> R_q) + EV phase B partials for q
        transfer_p2(Aq, Renv, Msct, t);
        {
            const float2* Lp = Lenv + (q-1)*256;
            const int bp = t & 15, s = (t >> 4) & 1, a2a = t >> 5;
            float num = 0.f, den = 0.f;
#pragma unroll
            for (int h = 0; h < 2; ++h) {
                const int a2 = a2a + h*8;
                float2 ze = make_float2(0.f,0.f), zo = make_float2(0.f,0.f);
#pragma unroll
                for (int al = 0; al < 16; al += 2) {
                    cmac(ze, Lp[(al  )*16 + a2], Msc[((al  )*2 + s)*16 + bp]);
                    cmac(zo, Lp[(al+1)*16 + a2], Msc[((al+1)*2 + s)*16 + bp]);
                }
                float2 z = make_float2(ze.x + zo.x, ze.y + zo.y);
                float2 av = Aq[(a2*2 + s)*ST + bp];
                float v = z.x*av.x + z.y*av.y;
                num += s ? -v : v;  den += v;
            }
#pragma unroll
            for (int o = 16; o > 0; o >>= 1) {
                num += __shfl_xor_sync(0xffffffffu, num, o);
                den += __shfl_xor_sync(0xffffffffu, den, o);
            }
            if (lane == 0) { red[wid*2] = num; red[wid*2+1] = den; }
        }
        __syncthreads();

        // fused phase: write out[q] + phase A for q-1 (uses new Renv = R_q)
        if (t == 0) {
            float N = 0.f, D = 0.f;
#pragma unroll
            for (int wdx = 0; wdx < 8; ++wdx) { N += red[wdx*2]; D += red[wdx*2+1]; }
            out[b*4 + q] = N / D;
        }
        transfer_p1(A + (q-1)*SITE, Renv, Msct, Msc, t);
        __syncthreads();
    }

    // q = 0: phase B only (site 0 left dim 1; rows (al=0,s) of Msc)
    {
        float num = 0.f, den = 0.f;
        if (t < 32) {
            const int s = t >> 4, bp = t & 15;
            float2 z  = Msc[s*16 + bp];
            float2 av = A[s*ST + bp];
            float v = z.x*av.x + z.y*av.y;
            num = s ? -v : v;  den = v;
        }
#pragma unroll
        for (int o = 16; o > 0; o >>= 1) {
            num += __shfl_xor_sync(0xffffffffu, num, o);
            den += __shfl_xor_sync(0xffffffffu, den, o);
        }
        if (lane == 0) { red[wid*2] = num; red[wid*2+1] = den; }
    }
    __syncthreads();
    if (t == 0) {
        float N = 0.f, D = 0.f;
#pragma unroll
        for (int wdx = 0; wdx < 8; ++wdx) { N += red[wdx*2]; D += red[wdx*2+1]; }
        out[b*4 + 0] = N / D;
    }
}

extern "C" void kernel_launch(void* const* d_in, const int* in_sizes, int n_in,
                              void* d_out, int out_size) {
    const float* w;
    const int*   xin;
    if (n_in >= 2 && in_sizes[0] == 4*18*3) {
        w   = (const float*)d_in[0];
        xin = (const int*)  d_in[1];
    } else {
        w   = (const float*)d_in[1];
        xin = (const int*)  d_in[0];
    }
    float* out = (float*)d_out;

    cudaFuncSetAttribute(vqc_mps_kernel,
                         cudaFuncAttributeMaxDynamicSharedMemorySize,
                         (int)SMEM_BYTES);
    vqc_mps_kernel<<<64, TPB, SMEM_BYTES>>>(w, xin, out);
}

// round 7
// speedup vs baseline: 1.1385x; 1.0749x over previous
#include <cuda_runtime.h>

#define TPB  256
#define ST   17            // padded row stride (float2 units)
#define SITE (32*ST)       // 544 float2 per site tensor

__device__ __forceinline__ void cmac(float2& acc, float2 a, float2 b) {        // acc += a*b
    acc.x = fmaf(a.x, b.x, fmaf(-a.y, b.y, acc.x));
    acc.y = fmaf(a.x, b.y, fmaf( a.y, b.x, acc.y));
}
__device__ __forceinline__ void cmacc(float2& acc, float2 a, float2 b) {       // acc += a*conj(b)
    acc.x = fmaf(a.x, b.x, fmaf( a.y, b.y, acc.x));
    acc.y = fmaf(a.y, b.x, fmaf(-a.x, b.y, acc.y));
}

// smem: bufA 18*544 | bufB 18*544 | Ush 72 | Msct 544 | Msc 512 | Renv 256 | Renv2 256 | Lenv 768 | red 16f
#define F2_TOTAL (2*18*SITE + 72 + SITE + 512 + 256 + 256 + 768)
#define SMEM_BYTES (F2_TOTAL*8 + 16*4)

// ---- warp-local fused transfer: Rout <- sum_s A . Rin . A^dag, ONE block barrier
// (caller supplies it). Warp w owns Rout rows a1 in {2w, 2w+1}; its needed M-slice
// (4 rows x 16) is computed in-warp into Wsc, synced with __syncwarp only.
__device__ __forceinline__ void transfer_fused(const float2* __restrict__ Aj,
                                               const float2* __restrict__ Rin,
                                               float2* __restrict__ Rout,
                                               float2* __restrict__ Wsc_all,
                                               int lane, int wid)
{
    float2* Wsc = Wsc_all + wid*64;
    const int bp = lane & 15;
    const int hi = lane >> 4;                 // step1: s = hi; step2: a1local = hi

    // step 1: M[(a1,s=hi)][bp] for a1 = 2w (r0) and 2w+1 (r1)
    const float2* r0 = Aj + (4*wid     + hi)*ST;
    const float2* r1 = Aj + (4*wid + 2 + hi)*ST;
    float2 m0a = {0,0}, m0b = {0,0}, m1a = {0,0}, m1b = {0,0};
#pragma unroll
    for (int be = 0; be < 16; be += 2) {
        float2 rv0 = Rin[ be   *16 + bp];
        float2 rv1 = Rin[(be+1)*16 + bp];
        cmac(m0a, r0[be],   rv0);  cmac(m0b, r0[be+1], rv1);
        cmac(m1a, r1[be],   rv0);  cmac(m1b, r1[be+1], rv1);
    }
    Wsc[ hi     *16 + bp] = make_float2(m0a.x+m0b.x, m0a.y+m0b.y);   // rl = 2*0+hi
    Wsc[(2+hi)  *16 + bp] = make_float2(m1a.x+m1b.x, m1a.y+m1b.y);   // rl = 2*1+hi
    __syncwarp();

    // step 2: Rout[a1][a2] = sum_{s,bp2} M[(a1,s)][bp2] * conj(A[(a2,s)][bp2])
    // a1 = 2w + hi, a2 = bp. M slice rows rl = 2*hi + s.
    const int a1 = 2*wid + hi;
    const float2* as0 = Aj + (bp*2)*ST;       // a2's s=0 row
    const float2* as1 = as0 + ST;             // a2's s=1 row
    const float2* M0 = Wsc + (2*hi    )*16;
    const float2* M1 = Wsc + (2*hi + 1)*16;
    float2 acc0 = {0,0}, acc1 = {0,0}, acc2 = {0,0}, acc3 = {0,0};
#pragma unroll
    for (int k = 0; k < 16; k += 2) {
        cmacc(acc0, M0[k],   as0[k]);
        cmacc(acc1, M0[k+1], as0[k+1]);
        cmacc(acc2, M1[k],   as1[k]);
        cmacc(acc3, M1[k+1], as1[k+1]);
    }
    Rout[a1*16 + bp] = make_float2(acc0.x+acc1.x+acc2.x+acc3.x,
                                   acc0.y+acc1.y+acc2.y+acc3.y);
}

// ---- two-phase transfer kept for the EV loop (needs full M in Msc) ----
__device__ __forceinline__ void transfer_p1(const float2* __restrict__ Aj,
                                            const float2* __restrict__ Renv,
                                            float2* __restrict__ Msct,
                                            float2* __restrict__ Msc, int t)
{
    const int r = t >> 3, bpq = t & 7, bp0 = bpq * 2;
    const float4* R4 = (const float4*)Renv;
    float4 rv[16];
#pragma unroll
    for (int be = 0; be < 16; ++be) rv[be] = R4[be*8 + bpq];

    const float2* row = Aj + r*ST;
    float2 e0 = {0,0}, o0 = {0,0}, e1 = {0,0}, o1 = {0,0};
#pragma unroll
    for (int be = 0; be < 16; be += 2) {
        float2 a0 = row[be], a1 = row[be+1];
        cmac(e0, a0, make_float2(rv[be].x,   rv[be].y));
        cmac(e1, a0, make_float2(rv[be].z,   rv[be].w));
        cmac(o0, a1, make_float2(rv[be+1].x, rv[be+1].y));
        cmac(o1, a1, make_float2(rv[be+1].z, rv[be+1].w));
    }
    const float2 out0 = make_float2(e0.x + o0.x, e0.y + o0.y);
    const float2 out1 = make_float2(e1.x + o1.x, e1.y + o1.y);
    const int s = r & 1, al = r >> 1;
    Msct[(s*16 + bp0  )*ST + al] = make_float2(out0.x, -out0.y);
    Msct[(s*16 + bp0+1)*ST + al] = make_float2(out1.x, -out1.y);
    Msc[r*16 + bp0  ] = out0;
    Msc[r*16 + bp0+1] = out1;
}

__device__ __forceinline__ void transfer_p2(const float2* __restrict__ Aj,
                                            float2* __restrict__ Renv,
                                            const float2* __restrict__ Msct, int t)
{
    const int a1 = t & 15, a2 = t >> 4;
    const float2* ar0 = Aj + (a2*2)*ST;
    const float2* ar1 = ar0 + ST;
    float2 p0 = {0,0}, p1 = {0,0}, p2 = {0,0}, p3 = {0,0};
#pragma unroll
    for (int c = 0; c < 16; c += 2) {
        cmac(p0, ar0[c  ], Msct[(c   )*ST + a1]);
        cmac(p1, ar0[c+1], Msct[(c+1 )*ST + a1]);
        cmac(p2, ar1[c  ], Msct[(16+c)*ST + a1]);
        cmac(p3, ar1[c+1], Msct[(17+c)*ST + a1]);
    }
    Renv[a1*16 + a2] = make_float2(p0.x+p1.x+p2.x+p3.x, -(p0.y+p1.y+p2.y+p3.y));
}

__global__ void __launch_bounds__(TPB, 1) vqc_mps_kernel(
    const float* __restrict__ w, const int* __restrict__ x, float* __restrict__ out)
{
    extern __shared__ float2 sm[];
    float2* bufA  = sm;
    float2* bufB  = bufA + 18*SITE;
    float2* Ush   = bufB + 18*SITE;
    float2* Msct  = Ush + 72;
    float2* Msc   = Msct + SITE;
    float2* Renv  = Msc + 512;
    float2* Renv2 = Renv + 256;
    float2* Lenv  = Renv2 + 256;
    float*  red   = (float*)(Lenv + 768);

    const int b = blockIdx.x, t = threadIdx.x;
    const int lane = t & 31, wid = t >> 5;

    // product state |x_0..x_8, 0..0>
    if (t < 18) {
        int bit = (t < 9) ? x[b*9 + t] : 0;
        bufA[t*SITE + 0 ] = make_float2(bit == 0 ? 1.f : 0.f, 0.f);
        bufA[t*SITE + ST] = make_float2(bit == 1 ? 1.f : 0.f, 0.f);
    }
    __syncthreads();

    float2* A  = bufA;
    float2* Bb = bufB;

    // ---- 4 layers: fused (rotation + CNOT-staircase MPO), chi: c -> 2c ----
    for (int l = 0; l < 4; ++l) {
        const int c2 = 2 << l;
        const int cm = (1 << l) - 1;

        if (t < 18) {
            float phi = w[(l*18 + t)*3 + 0];
            float th  = w[(l*18 + t)*3 + 1];
            float om  = w[(l*18 + t)*3 + 2];
            float sh, ch; sincosf(0.5f*th, &sh, &ch);
            float sa, ca; sincosf(-0.5f*(phi + om), &sa, &ca);
            float sb, cb; sincosf( 0.5f*(phi - om), &sb, &cb);
            Ush[t*4+0] = make_float2( ca*ch,  sa*ch);
            Ush[t*4+1] = make_float2(-cb*sh, -sb*sh);
            Ush[t*4+2] = make_float2( cb*sh, -sb*sh);
            Ush[t*4+3] = make_float2( ca*ch, -sa*ch);
        }
        __syncthreads();

        for (int j = 0; j < 18; ++j) {
            const int Lo = (j == 0)  ? 1 : c2;
            const int Ro = (j == 17) ? 1 : c2;
            const int n  = Lo * 2 * Ro;
            const float2* Aj = A  + j*SITE;
            float2*       Bj = Bb + j*SITE;
            const float2 U00 = Ush[j*4+0], U01 = Ush[j*4+1];
            const float2 U10 = Ush[j*4+2], U11 = Ush[j*4+3];
            for (int i = t; i < n; i += TPB) {
                int bp, rest;
                if (j == 17) { bp = 0;           rest = i; }
                else         { bp = i & (c2-1);  rest = i >> (l+1); }
                const int s  = rest & 1;
                const int ap = rest >> 1;
                const int a  = (j == 0)  ? 0 : (ap >> l);
                const int al = (j == 0)  ? 0 : (ap & cm);
                const int kb = (j == 17) ? s : (bp >> l);
                const int be = (j == 17) ? 0 : (bp & cm);
                float2 v = make_float2(0.f, 0.f);
                if (kb == s) {
                    const int u = s ^ a;
                    float2 A0 = Aj[al*(2*ST) + be];
                    float2 A1 = Aj[al*(2*ST) + ST + be];
                    float2 Ua = (u == 0) ? U00 : U10;
                    float2 Ub = (u == 0) ? U01 : U11;
                    cmac(v, Ua, A0);
                    cmac(v, Ub, A1);
                }
                Bj[(ap*2 + s)*ST + bp] = v;
            }
        }
        __syncthreads();
        float2* tmp = A; A = Bb; Bb = tmp;
    }

    // ---- fused phase: Renv init (site 17 Gram) + L0 init ----
    {
        const int i1 = t >> 4, i2 = t & 15;
        const float2* A17 = A + 17*SITE;
        float2 acc = make_float2(0.f,0.f);
        cmacc(acc, A17[(i1*2  )*ST], A17[(i2*2  )*ST]);
        cmacc(acc, A17[(i1*2+1)*ST], A17[(i2*2+1)*ST]);
        Renv[i1*16 + i2] = acc;

        const float2* A0 = A;
        float2 lcc = make_float2(0.f,0.f);
        cmacc(lcc, A0[i1],      A0[i2]);
        cmacc(lcc, A0[ST + i1], A0[ST + i2]);
        Lenv[t] = lcc;
    }
    __syncthreads();

    // ---- R-chain j = 16..4 : warp-fused, ONE barrier per transfer, ping-pong ----
    float2* Rcur = Renv;
    float2* Rnxt = Renv2;
    for (int j = 16; j >= 4; --j) {
        transfer_fused(A + j*SITE, Rcur, Rnxt, Msc, lane, wid);
        __syncthreads();
        float2* tmp = Rcur; Rcur = Rnxt; Rnxt = tmp;
    }

    // ---- left environments L1, L2 ----
    for (int m = 1; m <= 2; ++m) {
        const float2* Lp = Lenv + (m-1)*256;
        float2*       Ln = Lenv + m*256;
        const float2* Am = A + m*SITE;
        {
            const int g = t & 15, s = (t >> 4) & 1, b2a = t >> 5;
            float2 acc0 = {0,0}, acc1 = {0,0};
#pragma unroll
            for (int b1 = 0; b1 < 16; ++b1) {
                float2 av = Am[(b1*2 + s)*ST + g];
                cmac(acc0, Lp[b1*16 + b2a    ], av);
                cmac(acc1, Lp[b1*16 + b2a + 8], av);
            }
            Msc[ b2a     *32 + s*16 + g] = acc0;
            Msc[(b2a + 8)*32 + s*16 + g] = acc1;
        }
        __syncthreads();
        {
            const int g1 = t >> 4, g2 = t & 15;
            float2 acc = {0,0};
#pragma unroll
            for (int kk = 0; kk < 32; ++kk)
                cmacc(acc, Msc[(kk>>1)*32 + (kk&1)*16 + g1], Am[kk*ST + g2]);
            Ln[t] = acc;
        }
        __syncthreads();
    }

    // ---- EVs q=3..0 (phase A of q == transfer p1 of q, fused) ----
    transfer_p1(A + 3*SITE, Rcur, Msct, Msc, t);
    __syncthreads();

    for (int q = 3; q >= 1; --q) {
        const float2* Aq = A + q*SITE;

        // fused phase: transfer p2 (Rcur -> R_q, in place) + EV phase B partials
        transfer_p2(Aq, Rcur, Msct, t);
        {
            const float2* Lp = Lenv + (q-1)*256;
            const int bp = t & 15, s = (t >> 4) & 1, a2a = t >> 5;
            float num = 0.f, den = 0.f;
#pragma unroll
            for (int h = 0; h < 2; ++h) {
                const int a2 = a2a + h*8;
                float2 ze = {0,0}, zo = {0,0};
#pragma unroll
                for (int al = 0; al < 16; al += 2) {
                    cmac(ze, Lp[(al  )*16 + a2], Msc[((al  )*2 + s)*16 + bp]);
                    cmac(zo, Lp[(al+1)*16 + a2], Msc[((al+1)*2 + s)*16 + bp]);
                }
                float2 z = make_float2(ze.x + zo.x, ze.y + zo.y);
                float2 av = Aq[(a2*2 + s)*ST + bp];
                float v = z.x*av.x + z.y*av.y;
                num += s ? -v : v;  den += v;
            }
#pragma unroll
            for (int o = 16; o > 0; o >>= 1) {
                num += __shfl_xor_sync(0xffffffffu, num, o);
                den += __shfl_xor_sync(0xffffffffu, den, o);
            }
            if (lane == 0) { red[wid*2] = num; red[wid*2+1] = den; }
        }
        __syncthreads();

        // fused phase: write out[q] + phase A for q-1 (uses new Rcur = R_q)
        if (t == 0) {
            float N = 0.f, D = 0.f;
#pragma unroll
            for (int wdx = 0; wdx < 8; ++wdx) { N += red[wdx*2]; D += red[wdx*2+1]; }
            out[b*4 + q] = N / D;
        }
        transfer_p1(A + (q-1)*SITE, Rcur, Msct, Msc, t);
        __syncthreads();
    }

    // q = 0: phase B only (site 0 left dim 1)
    {
        float num = 0.f, den = 0.f;
        if (t < 32) {
            const int s = t >> 4, bp = t & 15;
            float2 z  = Msc[s*16 + bp];
            float2 av = A[s*ST + bp];
            float v = z.x*av.x + z.y*av.y;
            num = s ? -v : v;  den = v;
        }
#pragma unroll
        for (int o = 16; o > 0; o >>= 1) {
            num += __shfl_xor_sync(0xffffffffu, num, o);
            den += __shfl_xor_sync(0xffffffffu, den, o);
        }
        if (lane == 0) { red[wid*2] = num; red[wid*2+1] = den; }
    }
    __syncthreads();
    if (t == 0) {
        float N = 0.f, D = 0.f;
#pragma unroll
        for (int wdx = 0; wdx < 8; ++wdx) { N += red[wdx*2]; D += red[wdx*2+1]; }
        out[b*4 + 0] = N / D;
    }
}

extern "C" void kernel_launch(void* const* d_in, const int* in_sizes, int n_in,
                              void* d_out, int out_size) {
    const float* w;
    const int*   xin;
    if (n_in >= 2 && in_sizes[0] == 4*18*3) {
        w   = (const float*)d_in[0];
        xin = (const int*)  d_in[1];
    } else {
        w   = (const float*)d_in[1];
        xin = (const int*)  d_in[0];
    }
    float* out = (float*)d_out;

    cudaFuncSetAttribute(vqc_mps_kernel,
                         cudaFuncAttributeMaxDynamicSharedMemorySize,
                         (int)SMEM_BYTES);
    vqc_mps_kernel<<<64, TPB, SMEM_BYTES>>>(w, xin, out);
}

// round 8
// speedup vs baseline: 1.2078x; 1.0609x over previous
#include <cuda_runtime.h>

#define TPB  256
#define ST   18            // padded row stride (float2) — even => every row 16B-aligned
#define SITE (32*ST)       // 576 float2 per site tensor

__device__ __forceinline__ void cmac(float2& acc, float2 a, float2 b) {        // acc += a*b
    acc.x = fmaf(a.x, b.x, fmaf(-a.y, b.y, acc.x));
    acc.y = fmaf(a.x, b.y, fmaf( a.y, b.x, acc.y));
}
__device__ __forceinline__ void cmacc(float2& acc, float2 a, float2 b) {       // acc += a*conj(b)
    acc.x = fmaf(a.x, b.x, fmaf( a.y, b.y, acc.x));
    acc.y = fmaf(a.y, b.x, fmaf(-a.x, b.y, acc.y));
}
__device__ __forceinline__ float2 f2lo(float4 v) { return make_float2(v.x, v.y); }
__device__ __forceinline__ float2 f2hi(float4 v) { return make_float2(v.z, v.w); }

// smem layout (float2 units)
#define F2_TOTAL (2*18*SITE + 288 + SITE + 512 + 256 + 256 + 768)
#define SMEM_BYTES (F2_TOTAL*8 + 16*4)

// ---- warp-fused R transfer: Rout <- sum_s A . Rin . A^dag (one block barrier by caller)
__device__ __forceinline__ void transfer_fused(const float2* __restrict__ Aj,
                                               const float2* __restrict__ Rin,
                                               float2* __restrict__ Rout,
                                               float2* __restrict__ Wsc_all,
                                               int lane, int wid)
{
    float2* Wsc = Wsc_all + wid*64;
    const int bp = lane & 15;
    const int hi = lane >> 4;

    // step 1: M[(a1,s=hi)][bp] for a1 = 2w, 2w+1 (rows float4)
    const float4* r0f = (const float4*)(Aj + (4*wid     + hi)*ST);
    const float4* r1f = (const float4*)(Aj + (4*wid + 2 + hi)*ST);
    float2 m0a = {0,0}, m0b = {0,0}, m1a = {0,0}, m1b = {0,0};
#pragma unroll
    for (int be = 0; be < 16; be += 2) {
        float2 rv0 = Rin[ be   *16 + bp];
        float2 rv1 = Rin[(be+1)*16 + bp];
        float4 a0 = r0f[be>>1], a1 = r1f[be>>1];
        cmac(m0a, f2lo(a0), rv0);  cmac(m0b, f2hi(a0), rv1);
        cmac(m1a, f2lo(a1), rv0);  cmac(m1b, f2hi(a1), rv1);
    }
    Wsc[ hi   *16 + bp] = make_float2(m0a.x+m0b.x, m0a.y+m0b.y);
    Wsc[(2+hi)*16 + bp] = make_float2(m1a.x+m1b.x, m1a.y+m1b.y);
    __syncwarp();

    // step 2: Rout[a1][bp] = sum_{s,k} M[(a1,s)][k] * conj(A[(bp,s)][k]), a1 = 2w+hi
    const int a1 = 2*wid + hi;
    const float4* as0f = (const float4*)(Aj + (bp*2  )*ST);
    const float4* as1f = (const float4*)(Aj + (bp*2+1)*ST);
    const float4* M0f  = (const float4*)(Wsc + (2*hi    )*16);
    const float4* M1f  = (const float4*)(Wsc + (2*hi + 1)*16);
    float2 acc0 = {0,0}, acc1 = {0,0}, acc2 = {0,0}, acc3 = {0,0};
#pragma unroll
    for (int k = 0; k < 16; k += 2) {
        float4 a0 = as0f[k>>1], a1v = as1f[k>>1];
        float4 m0 = M0f[k>>1],  m1  = M1f[k>>1];
        cmacc(acc0, f2lo(m0), f2lo(a0));
        cmacc(acc1, f2hi(m0), f2hi(a0));
        cmacc(acc2, f2lo(m1), f2lo(a1v));
        cmacc(acc3, f2hi(m1), f2hi(a1v));
    }
    Rout[a1*16 + bp] = make_float2(acc0.x+acc1.x+acc2.x+acc3.x,
                                   acc0.y+acc1.y+acc2.y+acc3.y);
}

// ---- warp-fused L transfer: Lout[g1][g2] = sum_{b2,s} (sum_b1 Lin[b1][b2] A[(b1,s)][g1]) conj(A[(b2,s)][g2])
__device__ __forceinline__ void ltransfer_fused(const float2* __restrict__ Am,
                                                const float2* __restrict__ Lin,
                                                float2* __restrict__ Lout,
                                                float2* __restrict__ Wsc_all,
                                                int lane, int wid)
{
    float2* Wsc = Wsc_all + wid*64;
    const int g1a = 2*wid;
    {   // step 1: lane = (b2 = lane&15, s = lane>>4); M-cols g1a, g1a+1
        const int b2 = lane & 15, s = lane >> 4;
        float2 acc0 = {0,0}, acc1 = {0,0}, acc2 = {0,0}, acc3 = {0,0};
#pragma unroll
        for (int b1 = 0; b1 < 16; b1 += 2) {
            float2 lv0 = Lin[ b1   *16 + b2];
            float2 lv1 = Lin[(b1+1)*16 + b2];
            float4 av0 = *(const float4*)(Am + ( b1   *2 + s)*ST + g1a);
            float4 av1 = *(const float4*)(Am + ((b1+1)*2 + s)*ST + g1a);
            cmac(acc0, lv0, f2lo(av0));  cmac(acc1, lv0, f2hi(av0));
            cmac(acc2, lv1, f2lo(av1));  cmac(acc3, lv1, f2hi(av1));
        }
        Wsc[     s*16 + b2] = make_float2(acc0.x+acc2.x, acc0.y+acc2.y);  // g1loc 0
        Wsc[32 + s*16 + b2] = make_float2(acc1.x+acc3.x, acc1.y+acc3.y);  // g1loc 1
    }
    __syncwarp();
    {   // step 2: lane = (g2 = lane&15, g1loc = lane>>4)
        const int g2 = lane & 15, g1loc = lane >> 4;
        const float2* W = Wsc + g1loc*32;
        float2 p0 = {0,0}, p1 = {0,0};
#pragma unroll
        for (int k = 0; k < 32; k += 2) {
            const int r0 = (k&15)*2 + (k>>4);
            const int r1 = ((k+1)&15)*2 + ((k+1)>>4);
            cmacc(p0, W[k],   Am[r0*ST + g2]);
            cmacc(p1, W[k+1], Am[r1*ST + g2]);
        }
        Lout[(g1a + g1loc)*16 + g2] = make_float2(p0.x+p1.x, p0.y+p1.y);
    }
}

// ---- two-phase transfer for EV loop (needs full M in Msc) ----
__device__ __forceinline__ void transfer_p1(const float2* __restrict__ Aj,
                                            const float2* __restrict__ Renv,
                                            float2* __restrict__ Msct,
                                            float2* __restrict__ Msc, int t)
{
    const int r = t >> 3, bpq = t & 7, bp0 = bpq * 2;
    const float4* R4 = (const float4*)Renv;
    float4 rv[16];
#pragma unroll
    for (int be = 0; be < 16; ++be) rv[be] = R4[be*8 + bpq];

    const float4* rowf = (const float4*)(Aj + r*ST);
    float2 e0 = {0,0}, o0 = {0,0}, e1 = {0,0}, o1 = {0,0};
#pragma unroll
    for (int be = 0; be < 16; be += 2) {
        float4 a = rowf[be>>1];
        cmac(e0, f2lo(a), f2lo(rv[be]));
        cmac(e1, f2lo(a), f2hi(rv[be]));
        cmac(o0, f2hi(a), f2lo(rv[be+1]));
        cmac(o1, f2hi(a), f2hi(rv[be+1]));
    }
    const float2 out0 = make_float2(e0.x + o0.x, e0.y + o0.y);
    const float2 out1 = make_float2(e1.x + o1.x, e1.y + o1.y);
    const int s = r & 1, al = r >> 1;
    Msct[(s*16 + bp0  )*ST + al] = make_float2(out0.x, -out0.y);
    Msct[(s*16 + bp0+1)*ST + al] = make_float2(out1.x, -out1.y);
    Msc[r*16 + bp0  ] = out0;
    Msc[r*16 + bp0+1] = out1;
}

__device__ __forceinline__ void transfer_p2(const float2* __restrict__ Aj,
                                            float2* __restrict__ Renv,
                                            const float2* __restrict__ Msct, int t)
{
    const int a1 = t & 15, a2 = t >> 4;
    const float4* ar0f = (const float4*)(Aj + (a2*2  )*ST);
    const float4* ar1f = (const float4*)(Aj + (a2*2+1)*ST);
    float2 p0 = {0,0}, p1 = {0,0}, p2 = {0,0}, p3 = {0,0};
#pragma unroll
    for (int c = 0; c < 16; c += 2) {
        float4 av0 = ar0f[c>>1], av1 = ar1f[c>>1];
        cmac(p0, f2lo(av0), Msct[(c    )*ST + a1]);
        cmac(p1, f2hi(av0), Msct[(c+1  )*ST + a1]);
        cmac(p2, f2lo(av1), Msct[(16+c )*ST + a1]);
        cmac(p3, f2hi(av1), Msct[(17+c )*ST + a1]);
    }
    Renv[a1*16 + a2] = make_float2(p0.x+p1.x+p2.x+p3.x, -(p0.y+p1.y+p2.y+p3.y));
}

__global__ void __launch_bounds__(TPB, 1) vqc_mps_kernel(
    const float* __restrict__ w, const int* __restrict__ x, float* __restrict__ out)
{
    extern __shared__ float2 sm[];
    float2* bufA  = sm;
    float2* bufB  = bufA + 18*SITE;
    float2* Ush   = bufB + 18*SITE;     // 288: [l][j][4]
    float2* Msct  = Ush + 288;
    float2* Msc   = Msct + SITE;
    float2* Renv  = Msc + 512;
    float2* Renv2 = Renv + 256;
    float2* Lenv  = Renv2 + 256;
    float*  red   = (float*)(Lenv + 768);

    const int b = blockIdx.x, t = threadIdx.x;
    const int lane = t & 31, wid = t >> 5;

    // ---- init phase: product state + ALL 72 rotation matrices ----
    if (t < 72) {
        float phi = w[t*3 + 0];
        float th  = w[t*3 + 1];
        float om  = w[t*3 + 2];
        float sh, ch; sincosf(0.5f*th, &sh, &ch);
        float sa, ca; sincosf(-0.5f*(phi + om), &sa, &ca);
        float sb, cb; sincosf( 0.5f*(phi - om), &sb, &cb);
        Ush[t*4+0] = make_float2( ca*ch,  sa*ch);
        Ush[t*4+1] = make_float2(-cb*sh, -sb*sh);
        Ush[t*4+2] = make_float2( cb*sh, -sb*sh);
        Ush[t*4+3] = make_float2( ca*ch, -sa*ch);
    }
    if (t < 18) {
        int bit = (t < 9) ? x[b*9 + t] : 0;
        bufA[t*SITE + 0 ] = make_float2(bit == 0 ? 1.f : 0.f, 0.f);
        bufA[t*SITE + ST] = make_float2(bit == 1 ? 1.f : 0.f, 0.f);
    }
    __syncthreads();

    // ---- evolution: warp-per-site, all 4 layers, NO block barriers inside ----
    {
        int sites[3];
        sites[0] = wid; sites[1] = wid + 8; sites[2] = 16 + wid;
        const int ns = (wid < 2) ? 3 : 2;
        float2* cur = bufA;
        float2* nxt = bufB;
        for (int l = 0; l < 4; ++l) {
            const int c2 = 2 << l;
            const int cm = (1 << l) - 1;
            for (int si = 0; si < ns; ++si) {
                const int j = sites[si];
                const float2 U00 = Ush[(l*18+j)*4+0], U01 = Ush[(l*18+j)*4+1];
                const float2 U10 = Ush[(l*18+j)*4+2], U11 = Ush[(l*18+j)*4+3];
                const int Lo = (j == 0)  ? 1 : c2;
                const int Ro = (j == 17) ? 1 : c2;
                const int n  = Lo * 2 * Ro;
                const float2* Aj = cur + j*SITE;
                float2*       Bj = nxt + j*SITE;
                for (int i = lane; i < n; i += 32) {
                    int bp, rest;
                    if (j == 17) { bp = 0;           rest = i; }
                    else         { bp = i & (c2-1);  rest = i >> (l+1); }
                    const int s  = rest & 1;
                    const int ap = rest >> 1;
                    const int a  = (j == 0)  ? 0 : (ap >> l);
                    const int al = (j == 0)  ? 0 : (ap & cm);
                    const int kb = (j == 17) ? s : (bp >> l);
                    const int be = (j == 17) ? 0 : (bp & cm);
                    float2 v = make_float2(0.f, 0.f);
                    if (kb == s) {
                        const int u = s ^ a;
                        float2 A0 = Aj[al*(2*ST) + be];
                        float2 A1 = Aj[al*(2*ST) + ST + be];
                        float2 Ua = (u == 0) ? U00 : U10;
                        float2 Ub = (u == 0) ? U01 : U11;
                        cmac(v, Ua, A0);
                        cmac(v, Ub, A1);
                    }
                    Bj[(ap*2 + s)*ST + bp] = v;
                }
            }
            __syncwarp();
            float2* tmp = cur; cur = nxt; nxt = tmp;
        }
    }
    __syncthreads();
    float2* A = bufA;   // 4 swaps -> final state back in bufA

    // ---- fused phase: Renv init (site 17 Gram) + L0 init ----
    {
        const int i1 = t >> 4, i2 = t & 15;
        const float2* A17 = A + 17*SITE;
        float2 acc = {0,0};
        cmacc(acc, A17[(i1*2  )*ST], A17[(i2*2  )*ST]);
        cmacc(acc, A17[(i1*2+1)*ST], A17[(i2*2+1)*ST]);
        Renv[i1*16 + i2] = acc;

        float2 lcc = {0,0};
        cmacc(lcc, A[i1],      A[i2]);
        cmacc(lcc, A[ST + i1], A[ST + i2]);
        Lenv[t] = lcc;
    }
    __syncthreads();

    // ---- R-chain j = 16..4 : warp-fused, one barrier each, ping-pong ----
    float2* Rcur = Renv;
    float2* Rnxt = Renv2;
    for (int j = 16; j >= 4; --j) {
        transfer_fused(A + j*SITE, Rcur, Rnxt, Msc, lane, wid);
        __syncthreads();
        float2* tmp = Rcur; Rcur = Rnxt; Rnxt = tmp;
    }

    // ---- left environments L1, L2 : warp-fused, one barrier each ----
    ltransfer_fused(A + 1*SITE, Lenv,       Lenv + 256, Msc, lane, wid);
    __syncthreads();
    ltransfer_fused(A + 2*SITE, Lenv + 256, Lenv + 512, Msc, lane, wid);
    __syncthreads();

    // ---- EVs q=3..0 ----
    transfer_p1(A + 3*SITE, Rcur, Msct, Msc, t);
    __syncthreads();

    for (int q = 3; q >= 1; --q) {
        const float2* Aq = A + q*SITE;

        transfer_p2(Aq, Rcur, Msct, t);           // Rcur -> R_q in place
        {
            const float2* Lp = Lenv + (q-1)*256;
            const int bp = t & 15, s = (t >> 4) & 1, a2a = t >> 5;
            float num = 0.f, den = 0.f;
#pragma unroll
            for (int h = 0; h < 2; ++h) {
                const int a2 = a2a + h*8;
                float2 ze = {0,0}, zo = {0,0};
#pragma unroll
                for (int al = 0; al < 16; al += 2) {
                    cmac(ze, Lp[(al  )*16 + a2], Msc[((al  )*2 + s)*16 + bp]);
                    cmac(zo, Lp[(al+1)*16 + a2], Msc[((al+1)*2 + s)*16 + bp]);
                }
                float2 z = make_float2(ze.x + zo.x, ze.y + zo.y);
                float2 av = Aq[(a2*2 + s)*ST + bp];
                float v = z.x*av.x + z.y*av.y;
                num += s ? -v : v;  den += v;
            }
#pragma unroll
            for (int o = 16; o > 0; o >>= 1) {
                num += __shfl_xor_sync(0xffffffffu, num, o);
                den += __shfl_xor_sync(0xffffffffu, den, o);
            }
            if (lane == 0) { red[wid*2] = num; red[wid*2+1] = den; }
        }
        __syncthreads();

        if (t == 0) {
            float N = 0.f, D = 0.f;
#pragma unroll
            for (int wdx = 0; wdx < 8; ++wdx) { N += red[wdx*2]; D += red[wdx*2+1]; }
            out[b*4 + q] = N / D;
        }
        transfer_p1(A + (q-1)*SITE, Rcur, Msct, Msc, t);
        __syncthreads();
    }

    // q = 0
    {
        float num = 0.f, den = 0.f;
        if (t < 32) {
            const int s = t >> 4, bp = t & 15;
            float2 z  = Msc[s*16 + bp];
            float2 av = A[s*ST + bp];
            float v = z.x*av.x + z.y*av.y;
            num = s ? -v : v;  den = v;
        }
#pragma unroll
        for (int o = 16; o > 0; o >>= 1) {
            num += __shfl_xor_sync(0xffffffffu, num, o);
            den += __shfl_xor_sync(0xffffffffu, den, o);
        }
        if (lane == 0) { red[wid*2] = num; red[wid*2+1] = den; }
    }
    __syncthreads();
    if (t == 0) {
        float N = 0.f, D = 0.f;
#pragma unroll
        for (int wdx = 0; wdx < 8; ++wdx) { N += red[wdx*2]; D += red[wdx*2+1]; }
        out[b*4 + 0] = N / D;
    }
}

extern "C" void kernel_launch(void* const* d_in, const int* in_sizes, int n_in,
                              void* d_out, int out_size) {
    const float* w;
    const int*   xin;
    if (n_in >= 2 && in_sizes[0] == 4*18*3) {
        w   = (const float*)d_in[0];
        xin = (const int*)  d_in[1];
    } else {
        w   = (const float*)d_in[1];
        xin = (const int*)  d_in[0];
    }
    float* out = (float*)d_out;

    cudaFuncSetAttribute(vqc_mps_kernel,
                         cudaFuncAttributeMaxDynamicSharedMemorySize,
                         (int)SMEM_BYTES);
    vqc_mps_kernel<<<64, TPB, SMEM_BYTES>>>(w, xin, out);
}

// round 9
// speedup vs baseline: 1.2184x; 1.0088x over previous
#include <cuda_runtime.h>

#define TPB  256
#define ST   18            // padded row stride (float2) — even => every row 16B-aligned
#define SITE (32*ST)       // 576 float2 per site tensor

__device__ __forceinline__ void cmac(float2& acc, float2 a, float2 b) {        // acc += a*b
    acc.x = fmaf(a.x, b.x, fmaf(-a.y, b.y, acc.x));
    acc.y = fmaf(a.x, b.y, fmaf( a.y, b.x, acc.y));
}
__device__ __forceinline__ void cmacc(float2& acc, float2 a, float2 b) {       // acc += a*conj(b)
    acc.x = fmaf(a.x, b.x, fmaf( a.y, b.y, acc.x));
    acc.y = fmaf(a.y, b.x, fmaf(-a.x, b.y, acc.y));
}
__device__ __forceinline__ float2 f2lo(float4 v) { return make_float2(v.x, v.y); }
__device__ __forceinline__ float2 f2hi(float4 v) { return make_float2(v.z, v.w); }

// smem layout (float2 units)
#define F2_TOTAL (2*18*SITE + 288 + SITE + 512 + 256 + 256 + 768)
#define SMEM_BYTES (F2_TOTAL*8 + 16*4)

// ---- warp-fused R transfer: Rout <- sum_s A . Rin . A^dag (one block barrier by caller)
__device__ __forceinline__ void transfer_fused(const float2* __restrict__ Aj,
                                               const float2* __restrict__ Rin,
                                               float2* __restrict__ Rout,
                                               float2* __restrict__ Wsc_all,
                                               int lane, int wid)
{
    float2* Wsc = Wsc_all + wid*64;
    const int bp = lane & 15;
    const int hi = lane >> 4;

    // step 1: M[(a1,s=hi)][bp] for a1 = 2w, 2w+1 (rows float4)
    const float4* r0f = (const float4*)(Aj + (4*wid     + hi)*ST);
    const float4* r1f = (const float4*)(Aj + (4*wid + 2 + hi)*ST);
    float2 m0a = {0,0}, m0b = {0,0}, m1a = {0,0}, m1b = {0,0};
#pragma unroll
    for (int be = 0; be < 16; be += 2) {
        float2 rv0 = Rin[ be   *16 + bp];
        float2 rv1 = Rin[(be+1)*16 + bp];
        float4 a0 = r0f[be>>1], a1 = r1f[be>>1];
        cmac(m0a, f2lo(a0), rv0);  cmac(m0b, f2hi(a0), rv1);
        cmac(m1a, f2lo(a1), rv0);  cmac(m1b, f2hi(a1), rv1);
    }
    Wsc[ hi   *16 + bp] = make_float2(m0a.x+m0b.x, m0a.y+m0b.y);
    Wsc[(2+hi)*16 + bp] = make_float2(m1a.x+m1b.x, m1a.y+m1b.y);
    __syncwarp();

    // step 2: Rout[a1][bp] = sum_{s,k} M[(a1,s)][k] * conj(A[(bp,s)][k]), a1 = 2w+hi
    const int a1 = 2*wid + hi;
    const float4* as0f = (const float4*)(Aj + (bp*2  )*ST);
    const float4* as1f = (const float4*)(Aj + (bp*2+1)*ST);
    const float4* M0f  = (const float4*)(Wsc + (2*hi    )*16);
    const float4* M1f  = (const float4*)(Wsc + (2*hi + 1)*16);
    float2 acc0 = {0,0}, acc1 = {0,0}, acc2 = {0,0}, acc3 = {0,0};
#pragma unroll
    for (int k = 0; k < 16; k += 2) {
        float4 a0 = as0f[k>>1], a1v = as1f[k>>1];
        float4 m0 = M0f[k>>1],  m1  = M1f[k>>1];
        cmacc(acc0, f2lo(m0), f2lo(a0));
        cmacc(acc1, f2hi(m0), f2hi(a0));
        cmacc(acc2, f2lo(m1), f2lo(a1v));
        cmacc(acc3, f2hi(m1), f2hi(a1v));
    }
    Rout[a1*16 + bp] = make_float2(acc0.x+acc1.x+acc2.x+acc3.x,
                                   acc0.y+acc1.y+acc2.y+acc3.y);
}

// ---- warp-fused L transfer: Lout[g1][g2] = sum_{b2,s} (sum_b1 Lin[b1][b2] A[(b1,s)][g1]) conj(A[(b2,s)][g2])
__device__ __forceinline__ void ltransfer_fused(const float2* __restrict__ Am,
                                                const float2* __restrict__ Lin,
                                                float2* __restrict__ Lout,
                                                float2* __restrict__ Wsc_all,
                                                int lane, int wid)
{
    float2* Wsc = Wsc_all + wid*64;
    const int g1a = 2*wid;
    {   // step 1: lane = (b2 = lane&15, s = lane>>4); M-cols g1a, g1a+1
        const int b2 = lane & 15, s = lane >> 4;
        float2 acc0 = {0,0}, acc1 = {0,0}, acc2 = {0,0}, acc3 = {0,0};
#pragma unroll
        for (int b1 = 0; b1 < 16; b1 += 2) {
            float2 lv0 = Lin[ b1   *16 + b2];
            float2 lv1 = Lin[(b1+1)*16 + b2];
            float4 av0 = *(const float4*)(Am + ( b1   *2 + s)*ST + g1a);
            float4 av1 = *(const float4*)(Am + ((b1+1)*2 + s)*ST + g1a);
            cmac(acc0, lv0, f2lo(av0));  cmac(acc1, lv0, f2hi(av0));
            cmac(acc2, lv1, f2lo(av1));  cmac(acc3, lv1, f2hi(av1));
        }
        Wsc[     s*16 + b2] = make_float2(acc0.x+acc2.x, acc0.y+acc2.y);  // g1loc 0
        Wsc[32 + s*16 + b2] = make_float2(acc1.x+acc3.x, acc1.y+acc3.y);  // g1loc 1
    }
    __syncwarp();
    {   // step 2: lane = (g2 = lane&15, g1loc = lane>>4)
        const int g2 = lane & 15, g1loc = lane >> 4;
        const float2* W = Wsc + g1loc*32;
        float2 p0 = {0,0}, p1 = {0,0};
#pragma unroll
        for (int k = 0; k < 32; k += 2) {
            const int r0 = (k&15)*2 + (k>>4);
            const int r1 = ((k+1)&15)*2 + ((k+1)>>4);
            cmacc(p0, W[k],   Am[r0*ST + g2]);
            cmacc(p1, W[k+1], Am[r1*ST + g2]);
        }
        Lout[(g1a + g1loc)*16 + g2] = make_float2(p0.x+p1.x, p0.y+p1.y);
    }
}

// ---- two-phase transfer for EV loop (needs full M in Msc) ----
__device__ __forceinline__ void transfer_p1(const float2* __restrict__ Aj,
                                            const float2* __restrict__ Renv,
                                            float2* __restrict__ Msct,
                                            float2* __restrict__ Msc, int t)
{
    const int r = t >> 3, bpq = t & 7, bp0 = bpq * 2;
    const float4* R4 = (const float4*)Renv;
    float4 rv[16];
#pragma unroll
    for (int be = 0; be < 16; ++be) rv[be] = R4[be*8 + bpq];

    const float4* rowf = (const float4*)(Aj + r*ST);
    float2 e0 = {0,0}, o0 = {0,0}, e1 = {0,0}, o1 = {0,0};
#pragma unroll
    for (int be = 0; be < 16; be += 2) {
        float4 a = rowf[be>>1];
        cmac(e0, f2lo(a), f2lo(rv[be]));
        cmac(e1, f2lo(a), f2hi(rv[be]));
        cmac(o0, f2hi(a), f2lo(rv[be+1]));
        cmac(o1, f2hi(a), f2hi(rv[be+1]));
    }
    const float2 out0 = make_float2(e0.x + o0.x, e0.y + o0.y);
    const float2 out1 = make_float2(e1.x + o1.x, e1.y + o1.y);
    const int s = r & 1, al = r >> 1;
    Msct[(s*16 + bp0  )*ST + al] = make_float2(out0.x, -out0.y);
    Msct[(s*16 + bp0+1)*ST + al] = make_float2(out1.x, -out1.y);
    Msc[r*16 + bp0  ] = out0;
    Msc[r*16 + bp0+1] = out1;
}

__device__ __forceinline__ void transfer_p2(const float2* __restrict__ Aj,
                                            float2* __restrict__ Renv,
                                            const float2* __restrict__ Msct, int t)
{
    const int a1 = t & 15, a2 = t >> 4;
    const float4* ar0f = (const float4*)(Aj + (a2*2  )*ST);
    const float4* ar1f = (const float4*)(Aj + (a2*2+1)*ST);
    float2 p0 = {0,0}, p1 = {0,0}, p2 = {0,0}, p3 = {0,0};
#pragma unroll
    for (int c = 0; c < 16; c += 2) {
        float4 av0 = ar0f[c>>1], av1 = ar1f[c>>1];
        cmac(p0, f2lo(av0), Msct[(c    )*ST + a1]);
        cmac(p1, f2hi(av0), Msct[(c+1  )*ST + a1]);
        cmac(p2, f2lo(av1), Msct[(16+c )*ST + a1]);
        cmac(p3, f2hi(av1), Msct[(17+c )*ST + a1]);
    }
    Renv[a1*16 + a2] = make_float2(p0.x+p1.x+p2.x+p3.x, -(p0.y+p1.y+p2.y+p3.y));
}

__global__ void __launch_bounds__(TPB, 1) vqc_mps_kernel(
    const float* __restrict__ w, const int* __restrict__ x, float* __restrict__ out)
{
    extern __shared__ float2 sm[];
    float2* bufA  = sm;
    float2* bufB  = bufA + 18*SITE;
    float2* Ush   = bufB + 18*SITE;     // 288: [l][j][4]
    float2* Msct  = Ush + 288;
    float2* Msc   = Msct + SITE;
    float2* Renv  = Msc + 512;
    float2* Renv2 = Renv + 256;
    float2* Lenv  = Renv2 + 256;
    float*  red   = (float*)(Lenv + 768);

    const int b = blockIdx.x, t = threadIdx.x;
    const int lane = t & 31, wid = t >> 5;

    // ---- init phase: product state + ALL 72 rotation matrices ----
    if (t < 72) {
        float phi = w[t*3 + 0];
        float th  = w[t*3 + 1];
        float om  = w[t*3 + 2];
        float sh, ch; sincosf(0.5f*th, &sh, &ch);
        float sa, ca; sincosf(-0.5f*(phi + om), &sa, &ca);
        float sb, cb; sincosf( 0.5f*(phi - om), &sb, &cb);
        Ush[t*4+0] = make_float2( ca*ch,  sa*ch);
        Ush[t*4+1] = make_float2(-cb*sh, -sb*sh);
        Ush[t*4+2] = make_float2( cb*sh, -sb*sh);
        Ush[t*4+3] = make_float2( ca*ch, -sa*ch);
    }
    if (t < 18) {
        int bit = (t < 9) ? x[b*9 + t] : 0;
        bufA[t*SITE + 0 ] = make_float2(bit == 0 ? 1.f : 0.f, 0.f);
        bufA[t*SITE + ST] = make_float2(bit == 1 ? 1.f : 0.f, 0.f);
    }
    __syncthreads();

    // ---- evolution: warp-per-site, all 4 layers, NO block barriers inside ----
    {
        int sites[3];
        sites[0] = wid; sites[1] = wid + 8; sites[2] = 16 + wid;
        const int ns = (wid < 2) ? 3 : 2;
        float2* cur = bufA;
        float2* nxt = bufB;
        for (int l = 0; l < 4; ++l) {
            const int c2 = 2 << l;
            const int cm = (1 << l) - 1;
            for (int si = 0; si < ns; ++si) {
                const int j = sites[si];
                const float2 U00 = Ush[(l*18+j)*4+0], U01 = Ush[(l*18+j)*4+1];
                const float2 U10 = Ush[(l*18+j)*4+2], U11 = Ush[(l*18+j)*4+3];
                const int Lo = (j == 0)  ? 1 : c2;
                const int Ro = (j == 17) ? 1 : c2;
                const int n  = Lo * 2 * Ro;
                const float2* Aj = cur + j*SITE;
                float2*       Bj = nxt + j*SITE;
                for (int i = lane; i < n; i += 32) {
                    int bp, rest;
                    if (j == 17) { bp = 0;           rest = i; }
                    else         { bp = i & (c2-1);  rest = i >> (l+1); }
                    const int s  = rest & 1;
                    const int ap = rest >> 1;
                    const int a  = (j == 0)  ? 0 : (ap >> l);
                    const int al = (j == 0)  ? 0 : (ap & cm);
                    const int kb = (j == 17) ? s : (bp >> l);
                    const int be = (j == 17) ? 0 : (bp & cm);
                    float2 v = make_float2(0.f, 0.f);
                    if (kb == s) {
                        const int u = s ^ a;
                        float2 A0 = Aj[al*(2*ST) + be];
                        float2 A1 = Aj[al*(2*ST) + ST + be];
                        float2 Ua = (u == 0) ? U00 : U10;
                        float2 Ub = (u == 0) ? U01 : U11;
                        cmac(v, Ua, A0);
                        cmac(v, Ub, A1);
                    }
                    Bj[(ap*2 + s)*ST + bp] = v;
                }
            }
            __syncwarp();
            float2* tmp = cur; cur = nxt; nxt = tmp;
        }
    }
    __syncthreads();
    float2* A = bufA;   // 4 swaps -> final state back in bufA

    // ---- fused phase: Renv init (site 17 Gram) + L0 init ----
    {
        const int i1 = t >> 4, i2 = t & 15;
        const float2* A17 = A + 17*SITE;
        float2 acc = {0,0};
        cmacc(acc, A17[(i1*2  )*ST], A17[(i2*2  )*ST]);
        cmacc(acc, A17[(i1*2+1)*ST], A17[(i2*2+1)*ST]);
        Renv[i1*16 + i2] = acc;

        float2 lcc = {0,0};
        cmacc(lcc, A[i1],      A[i2]);
        cmacc(lcc, A[ST + i1], A[ST + i2]);
        Lenv[t] = lcc;
    }
    __syncthreads();

    // ---- R-chain j = 16..4 : warp-fused, one barrier each, ping-pong ----
    float2* Rcur = Renv;
    float2* Rnxt = Renv2;
    for (int j = 16; j >= 4; --j) {
        transfer_fused(A + j*SITE, Rcur, Rnxt, Msc, lane, wid);
        __syncthreads();
        float2* tmp = Rcur; Rcur = Rnxt; Rnxt = tmp;
    }

    // ---- left environments L1, L2 : warp-fused, one barrier each ----
    ltransfer_fused(A + 1*SITE, Lenv,       Lenv + 256, Msc, lane, wid);
    __syncthreads();
    ltransfer_fused(A + 2*SITE, Lenv + 256, Lenv + 512, Msc, lane, wid);
    __syncthreads();

    // ---- EVs q=3..0 ----
    transfer_p1(A + 3*SITE, Rcur, Msct, Msc, t);
    __syncthreads();

    for (int q = 3; q >= 1; --q) {
        const float2* Aq = A + q*SITE;

        transfer_p2(Aq, Rcur, Msct, t);           // Rcur -> R_q in place
        {
            const float2* Lp = Lenv + (q-1)*256;
            const int bp = t & 15, s = (t >> 4) & 1, a2a = t >> 5;
            float num = 0.f, den = 0.f;
#pragma unroll
            for (int h = 0; h < 2; ++h) {
                const int a2 = a2a + h*8;
                float2 ze = {0,0}, zo = {0,0};
#pragma unroll
                for (int al = 0; al < 16; al += 2) {
                    cmac(ze, Lp[(al  )*16 + a2], Msc[((al  )*2 + s)*16 + bp]);
                    cmac(zo, Lp[(al+1)*16 + a2], Msc[((al+1)*2 + s)*16 + bp]);
                }
                float2 z = make_float2(ze.x + zo.x, ze.y + zo.y);
                float2 av = Aq[(a2*2 + s)*ST + bp];
                float v = z.x*av.x + z.y*av.y;
                num += s ? -v : v;  den += v;
            }
#pragma unroll
            for (int o = 16; o > 0; o >>= 1) {
                num += __shfl_xor_sync(0xffffffffu, num, o);
                den += __shfl_xor_sync(0xffffffffu, den, o);
            }
            if (lane == 0) { red[wid*2] = num; red[wid*2+1] = den; }
        }
        __syncthreads();

        if (t == 0) {
            float N = 0.f, D = 0.f;
#pragma unroll
            for (int wdx = 0; wdx < 8; ++wdx) { N += red[wdx*2]; D += red[wdx*2+1]; }
            out[b*4 + q] = N / D;
        }
        transfer_p1(A + (q-1)*SITE, Rcur, Msct, Msc, t);
        __syncthreads();
    }

    // q = 0
    {
        float num = 0.f, den = 0.f;
        if (t < 32) {
            const int s = t >> 4, bp = t & 15;
            float2 z  = Msc[s*16 + bp];
            float2 av = A[s*ST + bp];
            float v = z.x*av.x + z.y*av.y;
            num = s ? -v : v;  den = v;
        }
#pragma unroll
        for (int o = 16; o > 0; o >>= 1) {
            num += __shfl_xor_sync(0xffffffffu, num, o);
            den += __shfl_xor_sync(0xffffffffu, den, o);
        }
        if (lane == 0) { red[wid*2] = num; red[wid*2+1] = den; }
    }
    __syncthreads();
    if (t == 0) {
        float N = 0.f, D = 0.f;
#pragma unroll
        for (int wdx = 0; wdx < 8; ++wdx) { N += red[wdx*2]; D += red[wdx*2+1]; }
        out[b*4 + 0] = N / D;
    }
}

extern "C" void kernel_launch(void* const* d_in, const int* in_sizes, int n_in,
                              void* d_out, int out_size) {
    const float* w;
    const int*   xin;
    if (n_in >= 2 && in_sizes[0] == 4*18*3) {
        w   = (const float*)d_in[0];
        xin = (const int*)  d_in[1];
    } else {
        w   = (const float*)d_in[1];
        xin = (const int*)  d_in[0];
    }
    float* out = (float*)d_out;

    cudaFuncSetAttribute(vqc_mps_kernel,
                         cudaFuncAttributeMaxDynamicSharedMemorySize,
                         (int)SMEM_BYTES);
    vqc_mps_kernel<<<64, TPB, SMEM_BYTES>>>(w, xin, out);
}

// round 11
// speedup vs baseline: 2.7820x; 2.2832x over previous
#include <cuda_runtime.h>

#define TPB   256
#define SST   10           // site row stride (float2); rows 16B-aligned
#define SSITE (16*SST)     // 160 f2 per site
#define WST   10

__device__ __forceinline__ void cmac(float2& c, float2 a, float2 b) {
    c.x = fmaf(a.x,b.x,fmaf(-a.y,b.y,c.x)); c.y = fmaf(a.x,b.y,fmaf(a.y,b.x,c.y));
}
__device__ __forceinline__ void cmacc(float2& c, float2 a, float2 b) { // a*conj(b)
    c.x = fmaf(a.x,b.x,fmaf(a.y,b.y,c.x));  c.y = fmaf(a.y,b.x,fmaf(-a.x,b.y,c.y));
}
__device__ __forceinline__ float2 f2lo(float4 v){return make_float2(v.x,v.y);}
__device__ __forceinline__ float2 f2hi(float4 v){return make_float2(v.z,v.w);}

#define F2_TOTAL (2*18*SSITE + 288 + 18*64 + 4*64 + 64 + 2*160)
#define SMEM_BYTES (F2_TOTAL*8 + 32*4)

// one chi=8 transfer, fully inside one warp. R[a1][a2] ket-first.
__device__ __forceinline__ void rtrans(const float2* __restrict__ Aj,
                                       const float2* __restrict__ Rin,
                                       float2* __restrict__ Rout,
                                       float2* __restrict__ Wsc, int lane)
{
    {   // step1: M[r=(a1,s)][be2] = sum_be A[r][be]*Rin[be][be2]
        const int r = lane >> 1, h = lane & 1;      // h: be2 half (4)
        const float4* R4 = (const float4*)Rin;
        const float2* arow = Aj + r*SST;
        float2 a0={0,0},a1={0,0},a2={0,0},a3={0,0};
#pragma unroll
        for (int be = 0; be < 8; ++be) {
            float2 av = arow[be];
            float4 r0 = R4[be*4 + 2*h], r1 = R4[be*4 + 2*h + 1];
            cmac(a0,av,f2lo(r0)); cmac(a1,av,f2hi(r0));
            cmac(a2,av,f2lo(r1)); cmac(a3,av,f2hi(r1));
        }
        float2* wr = Wsc + r*WST + 4*h;
        wr[0]=a0; wr[1]=a1; wr[2]=a2; wr[3]=a3;
    }
    __syncwarp();
    {   // step2: Rout[a1][a2] = sum_{s,be2(0..7)} M[(a1,s)][be2]*conj(A[(a2,s)][be2])
        const int a1i = lane >> 2, a2h = lane & 3;
        const float4* M0 = (const float4*)(Wsc + (2*a1i  )*WST);
        const float4* M1 = (const float4*)(Wsc + (2*a1i+1)*WST);
        float4 m0[4], m1[4];
#pragma unroll
        for (int k = 0; k < 4; ++k) { m0[k] = M0[k]; m1[k] = M1[k]; }
#pragma unroll
        for (int hh = 0; hh < 2; ++hh) {
            const int a2 = a2h + 4*hh;
            const float4* X0 = (const float4*)(Aj + (2*a2  )*SST);
            const float4* X1 = (const float4*)(Aj + (2*a2+1)*SST);
            float2 p0={0,0},p1={0,0},p2={0,0},p3={0,0};
#pragma unroll
            for (int k = 0; k < 4; ++k) {
                float4 x0 = X0[k], x1 = X1[k];
                cmacc(p0, f2lo(m0[k]), f2lo(x0));
                cmacc(p1, f2hi(m0[k]), f2hi(x0));
                cmacc(p2, f2lo(m1[k]), f2lo(x1));
                cmacc(p3, f2hi(m1[k]), f2hi(x1));
            }
            Rout[a1i*8 + a2] = make_float2(p0.x+p1.x+p2.x+p3.x, p0.y+p1.y+p2.y+p3.y);
        }
    }
    __syncwarp();
}

// L transfer with Z on physical leg:
// Lout[g1][g2] = sum_{b1,b2,s} (-1)^s Lin[b1][b2] A[(b1,s)][g1] conj(A[(b2,s)][g2])
__device__ __forceinline__ void ltrans(const float2* __restrict__ Am,
                                       const float2* __restrict__ Lin,
                                       float2* __restrict__ Lout,
                                       float2* __restrict__ Wsc, int lane)
{
    {   // step1: Y[q=(s,b2)][g1] = (-1)^s sum_b1 Lin[b1][b2]*A[(b1,s)][g1]
        const int q = lane >> 1, h = lane & 1;
        const int s = q >> 3, b2 = q & 7;
        float2 a0={0,0},a1={0,0},a2={0,0},a3={0,0};
#pragma unroll
        for (int b1 = 0; b1 < 8; ++b1) {
            float2 lv = Lin[b1*8 + b2];
            const float4* Ar = (const float4*)(Am + (b1*2+s)*SST);
            float4 w0 = Ar[2*h], w1 = Ar[2*h+1];
            cmac(a0,lv,f2lo(w0)); cmac(a1,lv,f2hi(w0));
            cmac(a2,lv,f2lo(w1)); cmac(a3,lv,f2hi(w1));
        }
        const float sg = s ? -1.f : 1.f;
        float2* wr = Wsc + q*WST + 4*h;
        wr[0]=make_float2(sg*a0.x,sg*a0.y); wr[1]=make_float2(sg*a1.x,sg*a1.y);
        wr[2]=make_float2(sg*a2.x,sg*a2.y); wr[3]=make_float2(sg*a3.x,sg*a3.y);
    }
    __syncwarp();
    {   // step2: Lout[g1][g2] = sum_q Y[q][g1]*conj(A[(b2,s)][g2])
        const int g1 = lane >> 2, g2h = lane & 3;
#pragma unroll
        for (int hh = 0; hh < 2; ++hh) {
            const int g2 = g2h + 4*hh;
            float2 p0={0,0},p1={0,0};
#pragma unroll
            for (int q = 0; q < 16; q += 2) {
                const int r0 = ((q  )&7)*2 + ((q  )>>3);
                const int r1 = ((q+1)&7)*2 + ((q+1)>>3);
                cmacc(p0, Wsc[(q  )*WST + g1], Am[r0*SST + g2]);
                cmacc(p1, Wsc[(q+1)*WST + g1], Am[r1*SST + g2]);
            }
            Lout[g1*8+g2] = make_float2(p0.x+p1.x, p0.y+p1.y);
        }
    }
    __syncwarp();
}

__device__ __forceinline__ float dot64_re(const float2* L, const float2* R, int lane) {
    float2 l0=L[lane], r0=R[lane], l1=L[lane+32], r1=R[lane+32];
    float v = l0.x*r0.x - l0.y*r0.y + l1.x*r1.x - l1.y*r1.y;
#pragma unroll
    for (int o = 16; o > 0; o >>= 1) v += __shfl_xor_sync(0xffffffffu, v, o);
    return v;
}

__global__ void __launch_bounds__(TPB, 1) vqc_mps_kernel(
    const float* __restrict__ w, const int* __restrict__ x, float* __restrict__ out)
{
    extern __shared__ float2 sm[];
    float2* bufA = sm;
    float2* bufB = bufA + 18*SSITE;
    float2* Ush  = bufB + 18*SSITE;
    float2* Rb   = Ush + 288;          // slot j at Rb + j*64 (j=1..17)
    float2* LZ   = Rb + 18*64;         // LZ_q at LZ + q*64
    float2* L0p  = LZ + 256;
    float2* Wsc  = L0p + 64;           // 2 warp slices of 160
    float*  red  = (float*)(Wsc + 320);

    const int b = blockIdx.x, t = threadIdx.x;
    const int lane = t & 31, wid = t >> 5;

    if (t < 72) {
        float phi = w[t*3+0], th = w[t*3+1], om = w[t*3+2];
        float sh,ch; sincosf(0.5f*th,&sh,&ch);
        float sa,ca; sincosf(-0.5f*(phi+om),&sa,&ca);
        float sb,cb; sincosf( 0.5f*(phi-om),&sb,&cb);
        Ush[t*4+0]=make_float2( ca*ch, sa*ch);  Ush[t*4+1]=make_float2(-cb*sh,-sb*sh);
        Ush[t*4+2]=make_float2( cb*sh,-sb*sh);  Ush[t*4+3]=make_float2( ca*ch,-sa*ch);
    }
    if (t < 18) {
        int bit = (t < 9) ? x[b*9 + t] : 0;
        bufA[t*SSITE      ] = make_float2(bit==0?1.f:0.f, 0.f);
        bufA[t*SSITE + SST] = make_float2(bit==1?1.f:0.f, 0.f);
    }
    __syncthreads();

    // ---- evolution: 3 full layers (rot+staircase MPO) + layer-3 rotations ONLY
    // (4th staircase folded into observable: C^dag Z_q C = Z_0..Z_q) ----
    {
        int sites[3] = {wid, wid+8, 16+wid};
        const int ns = (wid < 2) ? 3 : 2;
        float2* cur = bufA; float2* nxt = bufB;
        for (int l = 0; l < 3; ++l) {
            const int c2 = 2 << l, cm = (1 << l) - 1;
            for (int si = 0; si < ns; ++si) {
                const int j = sites[si];
                const float2 U00=Ush[(l*18+j)*4+0], U01=Ush[(l*18+j)*4+1];
                const float2 U10=Ush[(l*18+j)*4+2], U11=Ush[(l*18+j)*4+3];
                const int Lo=(j==0)?1:c2, Ro=(j==17)?1:c2, n=Lo*2*Ro;
                const float2* Aj = cur + j*SSITE;
                float2*       Bj = nxt + j*SSITE;
                for (int i = lane; i < n; i += 32) {
                    int bp, rest;
                    if (j == 17) { bp = 0; rest = i; }
                    else         { bp = i & (c2-1); rest = i >> (l+1); }
                    const int s = rest & 1, ap = rest >> 1;
                    const int a  = (j==0)?0:(ap>>l), al = (j==0)?0:(ap&cm);
                    const int kb = (j==17)?s:(bp>>l), be = (j==17)?0:(bp&cm);
                    float2 v = make_float2(0.f,0.f);
                    if (kb == s) {
                        const int u = s ^ a;
                        float2 A0 = Aj[al*(2*SST) + be], A1 = Aj[al*(2*SST) + SST + be];
                        cmac(v, (u==0)?U00:U10, A0);
                        cmac(v, (u==0)?U01:U11, A1);
                    }
                    Bj[(ap*2+s)*SST + bp] = v;
                }
            }
            __syncwarp();
            float2* tmp = cur; cur = nxt; nxt = tmp;
        }
        // layer-3 rotations, in place on cur (= bufB)
        for (int si = 0; si < ns; ++si) {
            const int j = sites[si];
            const float2 U00=Ush[(54+j)*4+0], U01=Ush[(54+j)*4+1];
            const float2 U10=Ush[(54+j)*4+2], U11=Ush[(54+j)*4+3];
            const int dl=(j==0)?1:8, dr=(j==17)?1:8, n=dl*dr;
            float2* Aj = cur + j*SSITE;
            for (int i = lane; i < n; i += 32) {
                const int al = i / dr, be = i % dr;
                float2* p0 = Aj + (al*2)*SST + be;
                float2* p1 = p0 + SST;
                float2 v0 = *p0, v1 = *p1;
                float2 o0 = {0,0}, o1 = {0,0};
                cmac(o0,U00,v0); cmac(o0,U01,v1);
                cmac(o1,U10,v0); cmac(o1,U11,v1);
                *p0 = o0; *p1 = o1;
            }
        }
    }
    __syncthreads();
    const float2* A = bufB;

    // ---- chains (warp-parallel, no block barriers inside) ----
    if (wid == 0) {
        const float2* A17 = A + 17*SSITE;
        const int a1i = lane >> 2, a2h = lane & 3;
        float2 k0 = A17[(2*a1i)*SST], k1 = A17[(2*a1i+1)*SST];
        float2* R17 = Rb + 17*64;
#pragma unroll
        for (int hh = 0; hh < 2; ++hh) {
            const int a2 = a2h + 4*hh;
            float2 acc = {0,0};
            cmacc(acc, k0, A17[(2*a2)*SST]);
            cmacc(acc, k1, A17[(2*a2+1)*SST]);
            R17[a1i*8 + a2] = acc;
        }
        __syncwarp();
        for (int j = 16; j >= 1; --j)
            rtrans(A + j*SSITE, Rb + (j+1)*64, Rb + j*64, Wsc, lane);
    } else if (wid == 1) {
        const int b1 = lane >> 2, b2h = lane & 3;
        float2 k0 = A[b1], k1 = A[SST + b1];
#pragma unroll
        for (int hh = 0; hh < 2; ++hh) {
            const int b2 = b2h + 4*hh;
            float2 acc = {0,0}, tq = {0,0};
            cmacc(acc, k0, A[b2]);
            cmacc(tq,  k1, A[SST + b2]);
            LZ[b1*8 + b2] = make_float2(acc.x - tq.x, acc.y - tq.y);
        }
        __syncwarp();
        for (int m = 1; m <= 3; ++m)
            ltrans(A + m*SSITE, LZ + (m-1)*64, LZ + m*64, Wsc + 160, lane);
    } else if (wid == 2) {
        const int b1 = lane >> 2, b2h = lane & 3;
        float2 k0 = A[b1], k1 = A[SST + b1];
#pragma unroll
        for (int hh = 0; hh < 2; ++hh) {
            const int b2 = b2h + 4*hh;
            float2 acc = {0,0};
            cmacc(acc, k0, A[b2]);
            cmacc(acc, k1, A[SST + b2]);
            L0p[b1*8 + b2] = acc;
        }
    }
    __syncthreads();

    // ---- EVs: num_q = <LZ_q, R_{q+1}>, den = <L0p, R_1> ----
    if (wid < 4) {
        float v = dot64_re(LZ + wid*64, Rb + (wid+1)*64, lane);
        if (lane == 0) red[wid] = v;
    } else if (wid == 4) {
        float v = dot64_re(L0p, Rb + 64, lane);
        if (lane == 0) red[4] = v;
    }
    __syncthreads();
    if (t < 4) out[b*4 + t] = red[t] / red[4];
}

extern "C" void kernel_launch(void* const* d_in, const int* in_sizes, int n_in,
                              void* d_out, int out_size) {
    const float* w;
    const int*   xin;
    if (n_in >= 2 && in_sizes[0] == 4*18*3) {
        w   = (const float*)d_in[0];
        xin = (const int*)  d_in[1];
    } else {
        w   = (const float*)d_in[1];
        xin = (const int*)  d_in[0];
    }
    float* out = (float*)d_out;

    cudaFuncSetAttribute(vqc_mps_kernel,
                         cudaFuncAttributeMaxDynamicSharedMemorySize,
                         (int)SMEM_BYTES);
    vqc_mps_kernel<<<64, TPB, SMEM_BYTES>>>(w, xin, out);
}

// round 12
// speedup vs baseline: 3.2081x; 1.1532x over previous
#include <cuda_runtime.h>

#define TPB   256
#define SST   10           // site row stride (float2); rows 16B-aligned
#define SSITE (16*SST)
#define WST   10

__device__ __forceinline__ void cmac(float2& c, float2 a, float2 b) {
    c.x = fmaf(a.x,b.x,fmaf(-a.y,b.y,c.x)); c.y = fmaf(a.x,b.y,fmaf(a.y,b.x,c.y));
}
__device__ __forceinline__ void cmacc(float2& c, float2 a, float2 b) { // a*conj(b)
    c.x = fmaf(a.x,b.x,fmaf(a.y,b.y,c.x));  c.y = fmaf(a.y,b.x,fmaf(-a.x,b.y,c.y));
}
__device__ __forceinline__ float2 f2lo(float4 v){return make_float2(v.x,v.y);}
__device__ __forceinline__ float2 f2hi(float4 v){return make_float2(v.z,v.w);}

#define F2_TOTAL (2*18*SSITE + 288 + 18*64 + 4*64 + 64 + 2*160)
#define SMEM_BYTES (F2_TOTAL*8 + 32*4)

// L transfer with Z on physical leg (single warp) — unchanged from R11 (verified)
__device__ __forceinline__ void ltrans(const float2* __restrict__ Am,
                                       const float2* __restrict__ Lin,
                                       float2* __restrict__ Lout,
                                       float2* __restrict__ Wsc, int lane)
{
    {   const int q = lane >> 1, h = lane & 1;
        const int s = q >> 3, b2 = q & 7;
        float2 a0={0,0},a1={0,0},a2={0,0},a3={0,0};
#pragma unroll
        for (int b1 = 0; b1 < 8; ++b1) {
            float2 lv = Lin[b1*8 + b2];
            const float4* Ar = (const float4*)(Am + (b1*2+s)*SST);
            float4 w0 = Ar[2*h], w1 = Ar[2*h+1];
            cmac(a0,lv,f2lo(w0)); cmac(a1,lv,f2hi(w0));
            cmac(a2,lv,f2lo(w1)); cmac(a3,lv,f2hi(w1));
        }
        const float sg = s ? -1.f : 1.f;
        float2* wr = Wsc + q*WST + 4*h;
        wr[0]=make_float2(sg*a0.x,sg*a0.y); wr[1]=make_float2(sg*a1.x,sg*a1.y);
        wr[2]=make_float2(sg*a2.x,sg*a2.y); wr[3]=make_float2(sg*a3.x,sg*a3.y);
    }
    __syncwarp();
    {   const int g1 = lane >> 2, g2h = lane & 3;
#pragma unroll
        for (int hh = 0; hh < 2; ++hh) {
            const int g2 = g2h + 4*hh;
            float2 p0={0,0},p1={0,0};
#pragma unroll
            for (int q = 0; q < 16; q += 2) {
                const int r0 = ((q  )&7)*2 + ((q  )>>3);
                const int r1 = ((q+1)&7)*2 + ((q+1)>>3);
                cmacc(p0, Wsc[(q  )*WST + g1], Am[r0*SST + g2]);
                cmacc(p1, Wsc[(q+1)*WST + g1], Am[r1*SST + g2]);
            }
            Lout[g1*8+g2] = make_float2(p0.x+p1.x, p0.y+p1.y);
        }
    }
    __syncwarp();
}

__device__ __forceinline__ float dot64_re(const float2* L, const float2* R, int lane) {
    float2 l0=L[lane], r0=R[lane], l1=L[lane+32], r1=R[lane+32];
    float v = l0.x*r0.x - l0.y*r0.y + l1.x*r1.x - l1.y*r1.y;
#pragma unroll
    for (int o = 16; o > 0; o >>= 1) v += __shfl_xor_sync(0xffffffffu, v, o);
    return v;
}

__global__ void __launch_bounds__(TPB, 1) vqc_mps_kernel(
    const float* __restrict__ w, const int* __restrict__ x, float* __restrict__ out)
{
    extern __shared__ float2 sm[];
    float2* bufA = sm;
    float2* bufB = bufA + 18*SSITE;
    float2* Ush  = bufB + 18*SSITE;
    float2* Rb   = Ush + 288;          // slot j at Rb + j*64 (j=1..17)
    float2* LZ   = Rb + 18*64;         // LZ_q at LZ + q*64
    float2* L0p  = LZ + 256;
    float2* Wsc  = L0p + 64;           // R-warps use [0,160); L warp uses [160,320)
    float*  red  = (float*)(Wsc + 320);

    const int b = blockIdx.x, t = threadIdx.x;
    const int lane = t & 31, wid = t >> 5;

    if (t < 72) {
        float phi = w[t*3+0], th = w[t*3+1], om = w[t*3+2];
        float sh,ch; sincosf(0.5f*th,&sh,&ch);
        float sa,ca; sincosf(-0.5f*(phi+om),&sa,&ca);
        float sb,cb; sincosf( 0.5f*(phi-om),&sb,&cb);
        Ush[t*4+0]=make_float2( ca*ch, sa*ch);  Ush[t*4+1]=make_float2(-cb*sh,-sb*sh);
        Ush[t*4+2]=make_float2( cb*sh,-sb*sh);  Ush[t*4+3]=make_float2( ca*ch,-sa*ch);
    }
    if (t < 18) {
        int bit = (t < 9) ? x[b*9 + t] : 0;
        bufA[t*SSITE      ] = make_float2(bit==0?1.f:0.f, 0.f);
        bufA[t*SSITE + SST] = make_float2(bit==1?1.f:0.f, 0.f);
    }
    __syncthreads();

    // ---- evolution: 3 full layers (rot+MPO) + layer-3 rotations only
    // (4th staircase folded into observable: C^dag Z_q C = Z_0..Z_q) ----
    {
        int sites[3] = {wid, wid+8, 16+wid};
        const int ns = (wid < 2) ? 3 : 2;
        float2* cur = bufA; float2* nxt = bufB;
        for (int l = 0; l < 3; ++l) {
            const int c2 = 2 << l, cm = (1 << l) - 1;
            for (int si = 0; si < ns; ++si) {
                const int j = sites[si];
                const float2 U00=Ush[(l*18+j)*4+0], U01=Ush[(l*18+j)*4+1];
                const float2 U10=Ush[(l*18+j)*4+2], U11=Ush[(l*18+j)*4+3];
                const int Lo=(j==0)?1:c2, Ro=(j==17)?1:c2, n=Lo*2*Ro;
                const float2* Aj = cur + j*SSITE;
                float2*       Bj = nxt + j*SSITE;
                for (int i = lane; i < n; i += 32) {
                    int bp, rest;
                    if (j == 17) { bp = 0; rest = i; }
                    else         { bp = i & (c2-1); rest = i >> (l+1); }
                    const int s = rest & 1, ap = rest >> 1;
                    const int a  = (j==0)?0:(ap>>l), al = (j==0)?0:(ap&cm);
                    const int kb = (j==17)?s:(bp>>l), be = (j==17)?0:(bp&cm);
                    float2 v = make_float2(0.f,0.f);
                    if (kb == s) {
                        const int u = s ^ a;
                        float2 A0 = Aj[al*(2*SST) + be], A1 = Aj[al*(2*SST) + SST + be];
                        cmac(v, (u==0)?U00:U10, A0);
                        cmac(v, (u==0)?U01:U11, A1);
                    }
                    Bj[(ap*2+s)*SST + bp] = v;
                }
            }
            __syncwarp();
            float2* tmp = cur; cur = nxt; nxt = tmp;
        }
        for (int si = 0; si < ns; ++si) {     // layer-3 rotations in place (bufB)
            const int j = sites[si];
            const float2 U00=Ush[(54+j)*4+0], U01=Ush[(54+j)*4+1];
            const float2 U10=Ush[(54+j)*4+2], U11=Ush[(54+j)*4+3];
            const int dl=(j==0)?1:8, dr=(j==17)?1:8, n=dl*dr;
            float2* Aj = cur + j*SSITE;
            for (int i = lane; i < n; i += 32) {
                const int al = i / dr, be = i % dr;
                float2* p0 = Aj + (al*2)*SST + be;
                float2* p1 = p0 + SST;
                float2 v0 = *p0, v1 = *p1;
                float2 o0 = {0,0}, o1 = {0,0};
                cmac(o0,U00,v0); cmac(o0,U01,v1);
                cmac(o1,U10,v0); cmac(o1,U11,v1);
                *p0 = o0; *p1 = o1;
            }
        }
    }
    __syncthreads();
    const float2* A = bufB;

    // ---- R-chain across warps 0-3 (named barrier 1, 128 threads);
    //      L-chains concurrent in warps 4 (LZ) and 5 (norm Gram) ----
    if (wid < 4) {
        const int t4 = t;                     // 0..127
        if (t4 < 64) {                        // R_17 init
            const int a1 = t4 >> 3, a2 = t4 & 7;
            const float2* A17 = A + 17*SSITE;
            float2 acc = {0,0};
            cmacc(acc, A17[(2*a1  )*SST], A17[(2*a2  )*SST]);
            cmacc(acc, A17[(2*a1+1)*SST], A17[(2*a2+1)*SST]);
            Rb[17*64 + t4] = acc;
        }
        asm volatile("bar.sync 1, 128;" ::: "memory");

        for (int j = 16; j >= 1; --j) {
            const float2* Aj  = A + j*SSITE;
            const float2* Rin = Rb + (j+1)*64;
            float2*       Rout= Rb + j*64;
            // step1: M[r][be2] = sum_be A[r][be]*Rin[be][be2]  (1 output/lane)
            {
                const int r = t4 >> 3, be2 = t4 & 7;
                const float4* Ar = (const float4*)(Aj + r*SST);
                float4 a01 = Ar[0], a23 = Ar[1], a45 = Ar[2], a67 = Ar[3];
                float2 e = {0,0}, o = {0,0};
                cmac(e, f2lo(a01), Rin[0*8+be2]);  cmac(o, f2hi(a01), Rin[1*8+be2]);
                cmac(e, f2lo(a23), Rin[2*8+be2]);  cmac(o, f2hi(a23), Rin[3*8+be2]);
                cmac(e, f2lo(a45), Rin[4*8+be2]);  cmac(o, f2hi(a45), Rin[5*8+be2]);
                cmac(e, f2lo(a67), Rin[6*8+be2]);  cmac(o, f2hi(a67), Rin[7*8+be2]);
                Wsc[r*WST + be2] = make_float2(e.x+o.x, e.y+o.y);
            }
            __syncwarp();   // warp w's step2 reads only M rows 4w..4w+3 (own rows)
            // step2: Rout[a1][a2] = sum_{s,be2} M[(2a1+s)][be2]*conj(A[(2a2+s)][be2])
            {
                const int p = t4 >> 1, s = t4 & 1;
                const int a1 = p >> 3, a2 = p & 7;
                const float4* Mr = (const float4*)(Wsc + (a1*2+s)*WST);
                const float4* Xr = (const float4*)(Aj + (a2*2+s)*SST);
                float4 m0=Mr[0], m1=Mr[1], m2=Mr[2], m3=Mr[3];   // be2 0..7
                float4 x0=Xr[0], x1=Xr[1], x2=Xr[2], x3=Xr[3];
                float2 e = {0,0}, o = {0,0};
                cmacc(e, f2lo(m0), f2lo(x0));  cmacc(o, f2hi(m0), f2hi(x0));
                cmacc(e, f2lo(m1), f2lo(x1));  cmacc(o, f2hi(m1), f2hi(x1));
                cmacc(e, f2lo(m2), f2lo(x2));  cmacc(o, f2hi(m2), f2hi(x2));
                cmacc(e, f2lo(m3), f2lo(x3));  cmacc(o, f2hi(m3), f2hi(x3));
                float vx = e.x + o.x, vy = e.y + o.y;
                vx += __shfl_xor_sync(0xffffffffu, vx, 1);   // sum over s
                vy += __shfl_xor_sync(0xffffffffu, vy, 1);
                if (s == 0) Rout[a1*8 + a2] = make_float2(vx, vy);
            }
            asm volatile("bar.sync 1, 128;" ::: "memory");
        }
    } else if (wid == 4) {
        // LZ_0 then LZ_1..LZ_3 (Z chain)
        const int b1 = lane >> 2, b2h = lane & 3;
        float2 k0 = A[b1], k1 = A[SST + b1];
#pragma unroll
        for (int hh = 0; hh < 2; ++hh) {
            const int b2 = b2h + 4*hh;
            float2 acc = {0,0}, tq = {0,0};
            cmacc(acc, k0, A[b2]);
            cmacc(tq,  k1, A[SST + b2]);
            LZ[b1*8 + b2] = make_float2(acc.x - tq.x, acc.y - tq.y);
        }
        __syncwarp();
        for (int m = 1; m <= 3; ++m)
            ltrans(A + m*SSITE, LZ + (m-1)*64, LZ + m*64, Wsc + 160, lane);
    } else if (wid == 5) {
        // L0 plain Gram (norm)
        const int b1 = lane >> 2, b2h = lane & 3;
        float2 k0 = A[b1], k1 = A[SST + b1];
#pragma unroll
        for (int hh = 0; hh < 2; ++hh) {
            const int b2 = b2h + 4*hh;
            float2 acc = {0,0};
            cmacc(acc, k0, A[b2]);
            cmacc(acc, k1, A[SST + b2]);
            L0p[b1*8 + b2] = acc;
        }
    }
    __syncthreads();

    // ---- EVs: num_q = <LZ_q, R_{q+1}>, den = <L0p, R_1> ----
    if (wid < 4) {
        float v = dot64_re(LZ + wid*64, Rb + (wid+1)*64, lane);
        if (lane == 0) red[wid] = v;
    } else if (wid == 4) {
        float v = dot64_re(L0p, Rb + 64, lane);
        if (lane == 0) red[4] = v;
    }
    __syncthreads();
    if (t < 4) out[b*4 + t] = red[t] / red[4];
}

extern "C" void kernel_launch(void* const* d_in, const int* in_sizes, int n_in,
                              void* d_out, int out_size) {
    const float* w;
    const int*   xin;
    if (n_in >= 2 && in_sizes[0] == 4*18*3) {
        w   = (const float*)d_in[0];
        xin = (const int*)  d_in[1];
    } else {
        w   = (const float*)d_in[1];
        xin = (const int*)  d_in[0];
    }
    float* out = (float*)d_out;

    cudaFuncSetAttribute(vqc_mps_kernel,
                         cudaFuncAttributeMaxDynamicSharedMemorySize,
                         (int)SMEM_BYTES);
    vqc_mps_kernel<<<64, TPB, SMEM_BYTES>>>(w, xin, out);
}

// round 13
// speedup vs baseline: 3.2267x; 1.0058x over previous
#include <cuda_runtime.h>

#define TPB   256
#define SST   10
#define SSITE (16*SST)
#define WST   10

__device__ __forceinline__ void cmac(float2& c, float2 a, float2 b) {
    c.x = fmaf(a.x,b.x,fmaf(-a.y,b.y,c.x)); c.y = fmaf(a.x,b.y,fmaf(a.y,b.x,c.y));
}
__device__ __forceinline__ void cmacc(float2& c, float2 a, float2 b) { // a*conj(b)
    c.x = fmaf(a.x,b.x,fmaf(a.y,b.y,c.x));  c.y = fmaf(a.y,b.x,fmaf(-a.x,b.y,c.y));
}
__device__ __forceinline__ float2 f2lo(float4 v){return make_float2(v.x,v.y);}
__device__ __forceinline__ float2 f2hi(float4 v){return make_float2(v.z,v.w);}

#define F2_TOTAL (2*18*SSITE + 288 + 18*64 + 4*64 + 64 + 2*160)
#define SMEM_BYTES (F2_TOTAL*8 + 32*4)

// L transfer with Z on physical leg (single warp) — verified in R11/R12
__device__ __forceinline__ void ltrans(const float2* __restrict__ Am,
                                       const float2* __restrict__ Lin,
                                       float2* __restrict__ Lout,
                                       float2* __restrict__ Wsc, int lane)
{
    {   const int q = lane >> 1, h = lane & 1;
        const int s = q >> 3, b2 = q & 7;
        float2 a0={0,0},a1={0,0},a2={0,0},a3={0,0};
#pragma unroll
        for (int b1 = 0; b1 < 8; ++b1) {
            float2 lv = Lin[b1*8 + b2];
            const float4* Ar = (const float4*)(Am + (b1*2+s)*SST);
            float4 w0 = Ar[2*h], w1 = Ar[2*h+1];
            cmac(a0,lv,f2lo(w0)); cmac(a1,lv,f2hi(w0));
            cmac(a2,lv,f2lo(w1)); cmac(a3,lv,f2hi(w1));
        }
        const float sg = s ? -1.f : 1.f;
        float2* wr = Wsc + q*WST + 4*h;
        wr[0]=make_float2(sg*a0.x,sg*a0.y); wr[1]=make_float2(sg*a1.x,sg*a1.y);
        wr[2]=make_float2(sg*a2.x,sg*a2.y); wr[3]=make_float2(sg*a3.x,sg*a3.y);
    }
    __syncwarp();
    {   const int g1 = lane >> 2, g2h = lane & 3;
#pragma unroll
        for (int hh = 0; hh < 2; ++hh) {
            const int g2 = g2h + 4*hh;
            float2 p0={0,0},p1={0,0};
#pragma unroll
            for (int q = 0; q < 16; q += 2) {
                const int r0 = ((q  )&7)*2 + ((q  )>>3);
                const int r1 = ((q+1)&7)*2 + ((q+1)>>3);
                cmacc(p0, Wsc[(q  )*WST + g1], Am[r0*SST + g2]);
                cmacc(p1, Wsc[(q+1)*WST + g1], Am[r1*SST + g2]);
            }
            Lout[g1*8+g2] = make_float2(p0.x+p1.x, p0.y+p1.y);
        }
    }
    __syncwarp();
}

__device__ __forceinline__ float dot64_re(const float2* L, const float2* R, int lane) {
    float2 l0=L[lane], r0=R[lane], l1=L[lane+32], r1=R[lane+32];
    float v = l0.x*r0.x - l0.y*r0.y + l1.x*r1.x - l1.y*r1.y;
#pragma unroll
    for (int o = 16; o > 0; o >>= 1) v += __shfl_xor_sync(0xffffffffu, v, o);
    return v;
}

__global__ void __launch_bounds__(TPB, 1) vqc_mps_kernel(
    const float* __restrict__ w, const int* __restrict__ x, float* __restrict__ out)
{
    extern __shared__ float2 sm[];
    float2* bufA = sm;
    float2* bufB = bufA + 18*SSITE;
    float2* Ush  = bufB + 18*SSITE;
    float2* Rb   = Ush + 288;
    float2* LZ   = Rb + 18*64;
    float2* L0p  = LZ + 256;
    float2* Wsc  = L0p + 64;
    float*  red  = (float*)(Wsc + 320);

    const int b = blockIdx.x, t = threadIdx.x;
    const int lane = t & 31, wid = t >> 5;

    if (t < 72) {
        float phi = w[t*3+0], th = w[t*3+1], om = w[t*3+2];
        float sh,ch; sincosf(0.5f*th,&sh,&ch);
        float sa,ca; sincosf(-0.5f*(phi+om),&sa,&ca);
        float sb,cb; sincosf( 0.5f*(phi-om),&sb,&cb);
        Ush[t*4+0]=make_float2( ca*ch, sa*ch);  Ush[t*4+1]=make_float2(-cb*sh,-sb*sh);
        Ush[t*4+2]=make_float2( cb*sh,-sb*sh);  Ush[t*4+3]=make_float2( ca*ch,-sa*ch);
    }
    if (t < 18) {
        int bit = (t < 9) ? x[b*9 + t] : 0;
        bufA[t*SSITE      ] = make_float2(bit==0?1.f:0.f, 0.f);
        bufA[t*SSITE + SST] = make_float2(bit==1?1.f:0.f, 0.f);
    }
    __syncthreads();

    // ---- evolution: 3 full layers (rot+MPO) + layer-3 rotations only ----
    {
        int sites[3] = {wid, wid+8, 16+wid};
        const int ns = (wid < 2) ? 3 : 2;
        float2* cur = bufA; float2* nxt = bufB;
        for (int l = 0; l < 3; ++l) {
            const int c2 = 2 << l, cm = (1 << l) - 1;
            for (int si = 0; si < ns; ++si) {
                const int j = sites[si];
                const float2 U00=Ush[(l*18+j)*4+0], U01=Ush[(l*18+j)*4+1];
                const float2 U10=Ush[(l*18+j)*4+2], U11=Ush[(l*18+j)*4+3];
                const int Lo=(j==0)?1:c2, Ro=(j==17)?1:c2, n=Lo*2*Ro;
                const float2* Aj = cur + j*SSITE;
                float2*       Bj = nxt + j*SSITE;
                for (int i = lane; i < n; i += 32) {
                    int bp, rest;
                    if (j == 17) { bp = 0; rest = i; }
                    else         { bp = i & (c2-1); rest = i >> (l+1); }
                    const int s = rest & 1, ap = rest >> 1;
                    const int a  = (j==0)?0:(ap>>l), al = (j==0)?0:(ap&cm);
                    const int kb = (j==17)?s:(bp>>l), be = (j==17)?0:(bp&cm);
                    float2 v = make_float2(0.f,0.f);
                    if (kb == s) {
                        const int u = s ^ a;
                        float2 A0 = Aj[al*(2*SST) + be], A1 = Aj[al*(2*SST) + SST + be];
                        cmac(v, (u==0)?U00:U10, A0);
                        cmac(v, (u==0)?U01:U11, A1);
                    }
                    Bj[(ap*2+s)*SST + bp] = v;
                }
            }
            __syncwarp();
            float2* tmp = cur; cur = nxt; nxt = tmp;
        }
        for (int si = 0; si < ns; ++si) {
            const int j = sites[si];
            const float2 U00=Ush[(54+j)*4+0], U01=Ush[(54+j)*4+1];
            const float2 U10=Ush[(54+j)*4+2], U11=Ush[(54+j)*4+3];
            const int dl=(j==0)?1:8, dr=(j==17)?1:8, n=dl*dr;
            float2* Aj = cur + j*SSITE;
            for (int i = lane; i < n; i += 32) {
                const int al = i / dr, be = i % dr;
                float2* p0 = Aj + (al*2)*SST + be;
                float2* p1 = p0 + SST;
                float2 v0 = *p0, v1 = *p1;
                float2 o0 = {0,0}, o1 = {0,0};
                cmac(o0,U00,v0); cmac(o0,U01,v1);
                cmac(o1,U10,v0); cmac(o1,U11,v1);
                *p0 = o0; *p1 = o1;
            }
        }
    }
    __syncthreads();
    const float2* A = bufB;

    // ---- R-chain warps 0-3 (pipelined); LZ chain warp 4; norm Gram warp 5 ----
    if (wid < 4) {
        const int t4 = t;
        const int r = t4 >> 3, be2 = t4 & 7;           // step1 identity
        const int p = t4 >> 1, s = t4 & 1;             // step2 identity
        const int a1 = p >> 3, a2 = p & 7;

        if (t4 < 64) {                                  // R_17 init
            const int i1 = t4 >> 3, i2 = t4 & 7;
            const float2* A17 = A + 17*SSITE;
            float2 acc = {0,0};
            cmacc(acc, A17[(2*i1  )*SST], A17[(2*i2  )*SST]);
            cmacc(acc, A17[(2*i1+1)*SST], A17[(2*i2+1)*SST]);
            Rb[17*64 + t4] = acc;
        }
        // preload site-16 A rows (step1: row r; step2: row 2a2+s)
        float4 s1r[4], s2r[4];
        {
            const float4* P1 = (const float4*)(A + 16*SSITE + r*SST);
            const float4* P2 = (const float4*)(A + 16*SSITE + (a2*2+s)*SST);
#pragma unroll
            for (int k = 0; k < 4; ++k) { s1r[k] = P1[k]; s2r[k] = P2[k]; }
        }
        asm volatile("bar.sync 1, 128;" ::: "memory");

        for (int j = 16; j >= 1; --j) {
            const float2* Rin = Rb + (j+1)*64;
            float2*       Rout= Rb + j*64;
            // step1: M[r][be2] = sum_be A[r][be]*Rin[be][be2]  (4 acc chains)
            {
                float2 rv[8];
#pragma unroll
                for (int be = 0; be < 8; ++be) rv[be] = Rin[be*8 + be2];
                float2 A0={0,0},A1={0,0},A2={0,0},A3={0,0};
                cmac(A0, f2lo(s1r[0]), rv[0]);  cmac(A1, f2hi(s1r[0]), rv[1]);
                cmac(A2, f2lo(s1r[1]), rv[2]);  cmac(A3, f2hi(s1r[1]), rv[3]);
                cmac(A0, f2lo(s1r[2]), rv[4]);  cmac(A1, f2hi(s1r[2]), rv[5]);
                cmac(A2, f2lo(s1r[3]), rv[6]);  cmac(A3, f2hi(s1r[3]), rv[7]);
                Wsc[r*WST + be2] = make_float2(A0.x+A1.x+A2.x+A3.x,
                                               A0.y+A1.y+A2.y+A3.y);
            }
            __syncwarp();
            // step2: Rout[a1][a2] = sum_{s,be2} M[(2a1+s)][be2]*conj(A[(2a2+s)][be2])
            {
                const float4* Mr = (const float4*)(Wsc + (a1*2+s)*WST);
                float4 m0=Mr[0], m1=Mr[1], m2=Mr[2], m3=Mr[3];
                float2 B0={0,0},B1={0,0},B2={0,0},B3={0,0};
                cmacc(B0, f2lo(m0), f2lo(s2r[0]));  cmacc(B1, f2hi(m0), f2hi(s2r[0]));
                cmacc(B2, f2lo(m1), f2lo(s2r[1]));  cmacc(B3, f2hi(m1), f2hi(s2r[1]));
                cmacc(B0, f2lo(m2), f2lo(s2r[2]));  cmacc(B1, f2hi(m2), f2hi(s2r[2]));
                cmacc(B2, f2lo(m3), f2lo(s2r[3]));  cmacc(B3, f2hi(m3), f2hi(s2r[3]));
                float vx = B0.x+B1.x+B2.x+B3.x, vy = B0.y+B1.y+B2.y+B3.y;
                vx += __shfl_xor_sync(0xffffffffu, vx, 1);
                vy += __shfl_xor_sync(0xffffffffu, vy, 1);
                if (s == 0) Rout[a1*8 + a2] = make_float2(vx, vy);
            }
            // prefetch next site's A rows before the barrier (overlaps drain)
            if (j > 1) {
                const float4* P1 = (const float4*)(A + (j-1)*SSITE + r*SST);
                const float4* P2 = (const float4*)(A + (j-1)*SSITE + (a2*2+s)*SST);
#pragma unroll
                for (int k = 0; k < 4; ++k) { s1r[k] = P1[k]; s2r[k] = P2[k]; }
            }
            asm volatile("bar.sync 1, 128;" ::: "memory");
        }
    } else if (wid == 4) {
        const int b1 = lane >> 2, b2h = lane & 3;
        float2 k0 = A[b1], k1 = A[SST + b1];
#pragma unroll
        for (int hh = 0; hh < 2; ++hh) {
            const int b2 = b2h + 4*hh;
            float2 acc = {0,0}, tq = {0,0};
            cmacc(acc, k0, A[b2]);
            cmacc(tq,  k1, A[SST + b2]);
            LZ[b1*8 + b2] = make_float2(acc.x - tq.x, acc.y - tq.y);
        }
        __syncwarp();
        for (int m = 1; m <= 3; ++m)
            ltrans(A + m*SSITE, LZ + (m-1)*64, LZ + m*64, Wsc + 160, lane);
    } else if (wid == 5) {
        const int b1 = lane >> 2, b2h = lane & 3;
        float2 k0 = A[b1], k1 = A[SST + b1];
#pragma unroll
        for (int hh = 0; hh < 2; ++hh) {
            const int b2 = b2h + 4*hh;
            float2 acc = {0,0};
            cmacc(acc, k0, A[b2]);
            cmacc(acc, k1, A[SST + b2]);
            L0p[b1*8 + b2] = acc;
        }
    }
    __syncthreads();

    // ---- EVs: num_q = <LZ_q, R_{q+1}>, den = <L0p, R_1> ----
    if (wid < 4) {
        float v = dot64_re(LZ + wid*64, Rb + (wid+1)*64, lane);
        if (lane == 0) red[wid] = v;
    } else if (wid == 4) {
        float v = dot64_re(L0p, Rb + 64, lane);
        if (lane == 0) red[4] = v;
    }
    __syncthreads();
    if (t < 4) out[b*4 + t] = red[t] / red[4];
}

extern "C" void kernel_launch(void* const* d_in, const int* in_sizes, int n_in,
                              void* d_out, int out_size) {
    const float* w;
    const int*   xin;
    if (n_in >= 2 && in_sizes[0] == 4*18*3) {
        w   = (const float*)d_in[0];
        xin = (const int*)  d_in[1];
    } else {
        w   = (const float*)d_in[1];
        xin = (const int*)  d_in[0];
    }
    float* out = (float*)d_out;

    cudaFuncSetAttribute(vqc_mps_kernel,
                         cudaFuncAttributeMaxDynamicSharedMemorySize,
                         (int)SMEM_BYTES);
    vqc_mps_kernel<<<64, TPB, SMEM_BYTES>>>(w, xin, out);
}

// round 14
// speedup vs baseline: 4.0809x; 1.2647x over previous
#include <cuda_runtime.h>

#define TPB   256
#define SST   10
#define SSITE (16*SST)
#define WST   10

__device__ __forceinline__ void cmac(float2& c, float2 a, float2 b) {
    c.x = fmaf(a.x,b.x,fmaf(-a.y,b.y,c.x)); c.y = fmaf(a.x,b.y,fmaf(a.y,b.x,c.y));
}
__device__ __forceinline__ void cmacc(float2& c, float2 a, float2 b) { // a*conj(b)
    c.x = fmaf(a.x,b.x,fmaf(a.y,b.y,c.x));  c.y = fmaf(a.y,b.x,fmaf(-a.x,b.y,c.y));
}
__device__ __forceinline__ float2 f2lo(float4 v){return make_float2(v.x,v.y);}
__device__ __forceinline__ float2 f2hi(float4 v){return make_float2(v.z,v.w);}

#define F2_TOTAL (18*SSITE + 288 + 18*64 + 4*64 + 64 + 2*160)
#define SMEM_BYTES (F2_TOTAL*8 + 32*4)

// L transfer with Z on physical leg (single warp) — verified R11-R13
__device__ __forceinline__ void ltrans(const float2* __restrict__ Am,
                                       const float2* __restrict__ Lin,
                                       float2* __restrict__ Lout,
                                       float2* __restrict__ Wsc, int lane)
{
    {   const int q = lane >> 1, h = lane & 1;
        const int s = q >> 3, b2 = q & 7;
        float2 a0={0,0},a1={0,0},a2={0,0},a3={0,0};
#pragma unroll
        for (int b1 = 0; b1 < 8; ++b1) {
            float2 lv = Lin[b1*8 + b2];
            const float4* Ar = (const float4*)(Am + (b1*2+s)*SST);
            float4 w0 = Ar[2*h], w1 = Ar[2*h+1];
            cmac(a0,lv,f2lo(w0)); cmac(a1,lv,f2hi(w0));
            cmac(a2,lv,f2lo(w1)); cmac(a3,lv,f2hi(w1));
        }
        const float sg = s ? -1.f : 1.f;
        float2* wr = Wsc + q*WST + 4*h;
        wr[0]=make_float2(sg*a0.x,sg*a0.y); wr[1]=make_float2(sg*a1.x,sg*a1.y);
        wr[2]=make_float2(sg*a2.x,sg*a2.y); wr[3]=make_float2(sg*a3.x,sg*a3.y);
    }
    __syncwarp();
    {   const int g1 = lane >> 2, g2h = lane & 3;
#pragma unroll
        for (int hh = 0; hh < 2; ++hh) {
            const int g2 = g2h + 4*hh;
            float2 p0={0,0},p1={0,0};
#pragma unroll
            for (int q = 0; q < 16; q += 2) {
                const int r0 = ((q  )&7)*2 + ((q  )>>3);
                const int r1 = ((q+1)&7)*2 + ((q+1)>>3);
                cmacc(p0, Wsc[(q  )*WST + g1], Am[r0*SST + g2]);
                cmacc(p1, Wsc[(q+1)*WST + g1], Am[r1*SST + g2]);
            }
            Lout[g1*8+g2] = make_float2(p0.x+p1.x, p0.y+p1.y);
        }
    }
    __syncwarp();
}

__device__ __forceinline__ float dot64_re(const float2* L, const float2* R, int lane) {
    float2 l0=L[lane], r0=R[lane], l1=L[lane+32], r1=R[lane+32];
    float v = l0.x*r0.x - l0.y*r0.y + l1.x*r1.x - l1.y*r1.y;
#pragma unroll
    for (int o = 16; o > 0; o >>= 1) v += __shfl_xor_sync(0xffffffffu, v, o);
    return v;
}

__global__ void __launch_bounds__(TPB, 1) vqc_mps_kernel(
    const float* __restrict__ w, const int* __restrict__ x, float* __restrict__ out)
{
    extern __shared__ float2 sm[];
    float2* S0   = sm;                 // state: 18 sites x SSITE
    float2* Ush  = S0 + 18*SSITE;      // 288
    float2* Rb   = Ush + 288;
    float2* LZ   = Rb + 18*64;
    float2* L0p  = LZ + 256;
    float2* Wsc  = L0p + 64;
    float*  red  = (float*)(Wsc + 320);

    const int b = blockIdx.x, t = threadIdx.x;
    const int lane = t & 31, wid = t >> 5;

    if (t < 72) {
        float phi = w[t*3+0], th = w[t*3+1], om = w[t*3+2];
        float sh,ch; sincosf(0.5f*th,&sh,&ch);
        float sa,ca; sincosf(-0.5f*(phi+om),&sa,&ca);
        float sb,cb; sincosf( 0.5f*(phi-om),&sb,&cb);
        Ush[t*4+0]=make_float2( ca*ch, sa*ch);  Ush[t*4+1]=make_float2(-cb*sh,-sb*sh);
        Ush[t*4+2]=make_float2( cb*sh,-sb*sh);  Ush[t*4+3]=make_float2( ca*ch,-sa*ch);
    }
    __syncthreads();

    // ---- evolution: CLOSED FORM. S[(a,v)][k] = U3[v][k2]*U2[k2^a2][k1]*U1[k1^a1][k0]*U0[k0^a0][bit]
    {
        int js[3]; int ns = 2;
        js[0] = wid; js[1] = wid + 8;
        if (wid == 0) { js[2] = 16; ns = 3; }
        if (wid == 1) { js[2] = 17; ns = 3; }
        for (int si = 0; si < ns; ++si) {
            const int j = js[si];
            const int bit = (j < 9) ? x[b*9 + j] : 0;
            const float2* U0 = Ush + j*4;
            const float2* U1 = Ush + (18+j)*4;
            const float2* U2 = Ush + (36+j)*4;
            const float2* U3 = Ush + (54+j)*4;
            float2* S = S0 + j*SSITE;
            if (j == 0) {
                if (lane < 16) {
                    const int v = lane >> 3, k = lane & 7;
                    const int k2 = k>>2, k1 = (k>>1)&1, k0 = k&1;
                    float2 e = {0,0}, f = {0,0}, g = {0,0};
                    cmac(e, U3[v*2+k2], U2[k2*2+k1]);
                    cmac(f, e, U1[k1*2+k0]);
                    cmac(g, f, U0[k0*2+bit]);
                    S[v*SST + k] = g;
                }
            } else if (j == 17) {
                if (lane < 16) {
                    const int a = lane >> 1, v = lane & 1;
                    const int a0 = a&1, a1 = (a>>1)&1, a2 = a>>2;
                    float2 v10 = U0[a0*2 + bit], v11 = U0[(1^a0)*2 + bit];
                    float2 w0={0,0}, w1={0,0};
                    cmac(w0, U1[a1*2+0],     v10); cmac(w0, U1[a1*2+1],     v11);
                    cmac(w1, U1[(1^a1)*2+0], v10); cmac(w1, U1[(1^a1)*2+1], v11);
                    float2 z0={0,0}, z1={0,0};
                    cmac(z0, U2[a2*2+0],     w0); cmac(z0, U2[a2*2+1],     w1);
                    cmac(z1, U2[(1^a2)*2+0], w0); cmac(z1, U2[(1^a2)*2+1], w1);
                    float2 f={0,0};
                    cmac(f, U3[v*2+0], z0); cmac(f, U3[v*2+1], z1);
                    S[(a*2+v)*SST] = f;
                }
            } else {
                const int r = lane >> 1, h = lane & 1;     // r=(a,v), k2=h
                const int a = r >> 1, v = r & 1;
                const int a0 = a&1, a1 = (a>>1)&1, a2 = a>>2;
                float2 t0 = U3[v*2 + h];
                float2 c0={0,0}, c1={0,0};
                cmac(c0, t0, U2[(h^a2)*2 + 0]);
                cmac(c1, t0, U2[(h^a2)*2 + 1]);
                float2 d00={0,0},d01={0,0},d10={0,0},d11={0,0};
                cmac(d00, c0, U1[a1*2+0]);     cmac(d01, c0, U1[a1*2+1]);
                cmac(d10, c1, U1[(1^a1)*2+0]); cmac(d11, c1, U1[(1^a1)*2+1]);
                float2 g0 = U0[a0*2 + bit], g1 = U0[(1^a0)*2 + bit];
                float2 e00={0,0},e01={0,0},e10={0,0},e11={0,0};
                cmac(e00, d00, g0); cmac(e01, d01, g1);
                cmac(e10, d10, g0); cmac(e11, d11, g1);
                float2* Srow = S + r*SST + h*4;
                Srow[0]=e00; Srow[1]=e01; Srow[2]=e10; Srow[3]=e11;
            }
        }
    }
    __syncthreads();
    const float2* A = S0;

    // ---- R-chain warps 0-3; LZ chain warp 4; norm Gram warp 5 (R13, verified) ----
    if (wid < 4) {
        const int t4 = t;
        const int r = t4 >> 3, be2 = t4 & 7;
        const int p = t4 >> 1, s = t4 & 1;
        const int a1 = p >> 3, a2 = p & 7;

        if (t4 < 64) {
            const int i1 = t4 >> 3, i2 = t4 & 7;
            const float2* A17 = A + 17*SSITE;
            float2 acc = {0,0};
            cmacc(acc, A17[(2*i1  )*SST], A17[(2*i2  )*SST]);
            cmacc(acc, A17[(2*i1+1)*SST], A17[(2*i2+1)*SST]);
            Rb[17*64 + t4] = acc;
        }
        float4 s1r[4], s2r[4];
        {
            const float4* P1 = (const float4*)(A + 16*SSITE + r*SST);
            const float4* P2 = (const float4*)(A + 16*SSITE + (a2*2+s)*SST);
#pragma unroll
            for (int k = 0; k < 4; ++k) { s1r[k] = P1[k]; s2r[k] = P2[k]; }
        }
        asm volatile("bar.sync 1, 128;" ::: "memory");

        for (int j = 16; j >= 1; --j) {
            const float2* Rin = Rb + (j+1)*64;
            float2*       Rout= Rb + j*64;
            {
                float2 rv[8];
#pragma unroll
                for (int be = 0; be < 8; ++be) rv[be] = Rin[be*8 + be2];
                float2 A0={0,0},A1={0,0},A2={0,0},A3={0,0};
                cmac(A0, f2lo(s1r[0]), rv[0]);  cmac(A1, f2hi(s1r[0]), rv[1]);
                cmac(A2, f2lo(s1r[1]), rv[2]);  cmac(A3, f2hi(s1r[1]), rv[3]);
                cmac(A0, f2lo(s1r[2]), rv[4]);  cmac(A1, f2hi(s1r[2]), rv[5]);
                cmac(A2, f2lo(s1r[3]), rv[6]);  cmac(A3, f2hi(s1r[3]), rv[7]);
                Wsc[r*WST + be2] = make_float2(A0.x+A1.x+A2.x+A3.x,
                                               A0.y+A1.y+A2.y+A3.y);
            }
            __syncwarp();
            {
                const float4* Mr = (const float4*)(Wsc + (a1*2+s)*WST);
                float4 m0=Mr[0], m1=Mr[1], m2=Mr[2], m3=Mr[3];
                float2 B0={0,0},B1={0,0},B2={0,0},B3={0,0};
                cmacc(B0, f2lo(m0), f2lo(s2r[0]));  cmacc(B1, f2hi(m0), f2hi(s2r[0]));
                cmacc(B2, f2lo(m1), f2lo(s2r[1]));  cmacc(B3, f2hi(m1), f2hi(s2r[1]));
                cmacc(B0, f2lo(m2), f2lo(s2r[2]));  cmacc(B1, f2hi(m2), f2hi(s2r[2]));
                cmacc(B2, f2lo(m3), f2lo(s2r[3]));  cmacc(B3, f2hi(m3), f2hi(s2r[3]));
                float vx = B0.x+B1.x+B2.x+B3.x, vy = B0.y+B1.y+B2.y+B3.y;
                vx += __shfl_xor_sync(0xffffffffu, vx, 1);
                vy += __shfl_xor_sync(0xffffffffu, vy, 1);
                if (s == 0) Rout[a1*8 + a2] = make_float2(vx, vy);
            }
            if (j > 1) {
                const float4* P1 = (const float4*)(A + (j-1)*SSITE + r*SST);
                const float4* P2 = (const float4*)(A + (j-1)*SSITE + (a2*2+s)*SST);
#pragma unroll
                for (int k = 0; k < 4; ++k) { s1r[k] = P1[k]; s2r[k] = P2[k]; }
            }
            asm volatile("bar.sync 1, 128;" ::: "memory");
        }
    } else if (wid == 4) {
        const int b1 = lane >> 2, b2h = lane & 3;
        float2 k0 = A[b1], k1 = A[SST + b1];
#pragma unroll
        for (int hh = 0; hh < 2; ++hh) {
            const int b2 = b2h + 4*hh;
            float2 acc = {0,0}, tq = {0,0};
            cmacc(acc, k0, A[b2]);
            cmacc(tq,  k1, A[SST + b2]);
            LZ[b1*8 + b2] = make_float2(acc.x - tq.x, acc.y - tq.y);
        }
        __syncwarp();
        for (int m = 1; m <= 3; ++m)
            ltrans(A + m*SSITE, LZ + (m-1)*64, LZ + m*64, Wsc + 160, lane);
    } else if (wid == 5) {
        const int b1 = lane >> 2, b2h = lane & 3;
        float2 k0 = A[b1], k1 = A[SST + b1];
#pragma unroll
        for (int hh = 0; hh < 2; ++hh) {
            const int b2 = b2h + 4*hh;
            float2 acc = {0,0};
            cmacc(acc, k0, A[b2]);
            cmacc(acc, k1, A[SST + b2]);
            L0p[b1*8 + b2] = acc;
        }
    }
    __syncthreads();

    // ---- EVs: num_q = <LZ_q, R_{q+1}>, den = <L0p, R_1> ----
    if (wid < 4) {
        float v = dot64_re(LZ + wid*64, Rb + (wid+1)*64, lane);
        if (lane == 0) red[wid] = v;
    } else if (wid == 4) {
        float v = dot64_re(L0p, Rb + 64, lane);
        if (lane == 0) red[4] = v;
    }
    __syncthreads();
    if (t < 4) out[b*4 + t] = red[t] / red[4];
}

extern "C" void kernel_launch(void* const* d_in, const int* in_sizes, int n_in,
                              void* d_out, int out_size) {
    const float* w;
    const int*   xin;
    if (n_in >= 2 && in_sizes[0] == 4*18*3) {
        w   = (const float*)d_in[0];
        xin = (const int*)  d_in[1];
    } else {
        w   = (const float*)d_in[1];
        xin = (const int*)  d_in[0];
    }
    float* out = (float*)d_out;

    cudaFuncSetAttribute(vqc_mps_kernel,
                         cudaFuncAttributeMaxDynamicSharedMemorySize,
                         (int)SMEM_BYTES);
    vqc_mps_kernel<<<64, TPB, SMEM_BYTES>>>(w, xin, out);
}